// round 10
// baseline (speedup 1.0000x reference)
#include <cuda_runtime.h>
#include <cuda_bf16.h>
#include <math.h>
#include <stdint.h>

#define T_STEPS 256
#define BATCH   256
#define OBSD    128
#define HIDD    256
#define HS      512
#define G4      2048
#define ACTD    16
#define TBROWS  (T_STEPS * BATCH)
#define NCTA    128
typedef __nv_bfloat16 BF;

// ---------------- scratch (static device arrays; no cudaMalloc) ----------------
__device__ __align__(16) float g_xgp[(size_t)TBROWS * G4];
__device__ __align__(16) BF    g_fHi[(size_t)TBROWS * HIDD];
__device__ __align__(16) BF    g_fLo[(size_t)TBROWS * HIDD];
__device__ __align__(16) BF    g_hHi[(size_t)TBROWS * HS];
__device__ __align__(16) BF    g_hLo[(size_t)TBROWS * HS];
__device__ __align__(16) BF    g_WhHi[(size_t)G4 * HS];      // [n][k] permuted+transposed
__device__ __align__(16) BF    g_WhLo[(size_t)G4 * HS];
__device__ __align__(16) BF    g_WiHi[(size_t)G4 * HIDD];
__device__ __align__(16) BF    g_WiLo[(size_t)G4 * HIDD];
__device__ __align__(16) float g_bP[G4];
// fine-grained producer flags: [mb 0..3][chunk 0..3], 128B apart (own L2 line each)
__device__ __align__(128) unsigned g_flag[16 * 32];

__device__ __forceinline__ float sigmf(float x) { return 1.0f / (1.0f + expf(-x)); }
__device__ __forceinline__ float geluf(float v) {
    float u = 0.7978845608028654f * (v + 0.044715f * v * v * v);
    return 0.5f * v * (1.0f + tanhf(u));
}
__device__ __forceinline__ uint32_t smem_u32(const void* p) {
    uint32_t a;
    asm("{ .reg .u64 t; cvta.to.shared.u64 t, %1; cvt.u32.u64 %0, t; }" : "=r"(a) : "l"(p));
    return a;
}
__device__ __forceinline__ void ldmx4(uint32_t addr, uint32_t* r) {
    asm volatile("ldmatrix.sync.aligned.m8n8.x4.shared.b16 {%0,%1,%2,%3}, [%4];"
        : "=r"(r[0]), "=r"(r[1]), "=r"(r[2]), "=r"(r[3]) : "r"(addr));
}
__device__ __forceinline__ void mma16816(float* d, const uint32_t* a, const uint32_t* b) {
    asm volatile("mma.sync.aligned.m16n8k16.row.col.f32.bf16.bf16.f32 "
        "{%0,%1,%2,%3}, {%4,%5,%6,%7}, {%8,%9}, {%0,%1,%2,%3};"
        : "+f"(d[0]), "+f"(d[1]), "+f"(d[2]), "+f"(d[3])
        : "r"(a[0]), "r"(a[1]), "r"(a[2]), "r"(a[3]), "r"(b[0]), "r"(b[1]));
}
#define CP_COMMIT() asm volatile("cp.async.commit_group;" ::: "memory")
#define CP_WAIT0()  asm volatile("cp.async.wait_group 0;" ::: "memory")
__device__ __forceinline__ void flag_arrive(unsigned* f) {
    asm volatile("red.release.gpu.global.add.u32 [%0], %1;" :: "l"(f), "r"(1u) : "memory");
}
__device__ __forceinline__ void flag_spin(const unsigned* f, unsigned target) {
    unsigned v;
    do {
        asm volatile("ld.acquire.gpu.global.u32 %0, [%1];" : "=r"(v) : "l"(f) : "memory");
    } while (v < target);
}

// A stage stride: 136 elems (272B, ≡16 mod 128 -> conflict-free ldmatrix)
#define AST 136
#define CHUNK_BYTES 17408          // 64 x 136 bf16
// ---- scan SMEM map (bytes) ----
#define S_W_HI  0
#define S_W_LO  66560
#define S_BUF0  133120             // [hi 17408][lo 17408]
#define S_BUF1  167936
#define S_PART  133120             // alias over both A buffers
#define S_CS    202752             // cell state 64x16 fp32
#define S_DYN   206848
#define WST_S   520
// ---- x_gates SMEM map ----
#define X_W_HI  0
#define X_W_LO  33792
#define X_BUF0  67584
#define X_BUF1  102400
#define X_PART  67584
#define X_DYN   137216
#define WST_X   264

// cp.async one K=128 chunk (64 rows) of A hi/lo into stage buffer
__device__ __forceinline__ void stage_cp(uint32_t dHi, uint32_t dLo,
                                         const BF* sHi, const BF* sLo,
                                         int ld, int tid) {
#pragma unroll
    for (int p = 0; p < 4; p++) {
        int j = tid + p * 256;
        int r = j >> 4, cb = j & 15;
        const BF* sh = sHi + (size_t)r * ld + cb * 8;
        const BF* sl = sLo + (size_t)r * ld + cb * 8;
        uint32_t dh = dHi + r * 272 + cb * 16;
        uint32_t dl = dLo + r * 272 + cb * 16;
        asm volatile("cp.async.cg.shared.global [%0], [%1], 16;\n\t"
                     "cp.async.cg.shared.global [%2], [%3], 16;"
                     :: "r"(dh), "l"(sh), "r"(dl), "l"(sl));
    }
}

// Warp (ng, kg): m64 x n32 tile, 2 ksteps of this chunk, 3 split passes.
__device__ __forceinline__ void mma_2ks(uint32_t aHi, uint32_t aLo,
                                        uint32_t wHi, uint32_t wLo, int wst,
                                        int kg, int gk0, int ng, int lane,
                                        float acc[4][4][4]) {
#pragma unroll
    for (int s = 0; s < 2; s++) {
        int lks = kg * 2 + s;
        int gks = gk0 + lks;
        uint32_t bh[2][4], bl[2][4];
#pragma unroll
        for (int h = 0; h < 2; h++) {
            int nrow = ng * 32 + h * 16 + (lane & 7) + ((lane >> 4) << 3);
            int kcol = gks * 16 + ((lane >> 3) & 1) * 8;
            ldmx4(wHi + (nrow * wst + kcol) * 2, bh[h]);
            ldmx4(wLo + (nrow * wst + kcol) * 2, bl[h]);
        }
#pragma unroll
        for (int mt = 0; mt < 4; mt++) {
            uint32_t ah[4], al[4];
            int row = mt * 16 + (lane & 15);
            int col = lks * 16 + ((lane >> 4) << 3);
            ldmx4(aHi + (row * AST + col) * 2, ah);
            ldmx4(aLo + (row * AST + col) * 2, al);
#pragma unroll
            for (int h = 0; h < 2; h++)
#pragma unroll
                for (int q = 0; q < 2; q++) {
                    int nt = h * 2 + q;
                    mma16816(acc[mt][nt], ah, &bh[h][q * 2]);
                    mma16816(acc[mt][nt], ah, &bl[h][q * 2]);
                    mma16816(acc[mt][nt], al, &bh[h][q * 2]);
                }
        }
    }
}

// STS k-split partials: part[kg][row 64][col 64], stride 68 floats
__device__ __forceinline__ void sts_part(float* part, float acc[4][4][4],
                                         int kg, int ng, int lane) {
#pragma unroll
    for (int mt = 0; mt < 4; mt++)
#pragma unroll
        for (int nt = 0; nt < 4; nt++) {
            int row0 = mt * 16 + (lane >> 2);
            int col = ng * 32 + nt * 8 + (lane & 3) * 2;
            *(float2*)&part[(kg * 64 + row0) * 68 + col] = *(float2*)&acc[mt][nt][0];
            *(float2*)&part[(kg * 64 + row0 + 8) * 68 + col] = *(float2*)&acc[mt][nt][2];
        }
}

// ---------------- prep ----------------
__global__ void prep_kernel(const float* __restrict__ Wi, const float* __restrict__ Wh,
                            const float* __restrict__ bl) {
    int stride = gridDim.x * blockDim.x;
    int idx = blockIdx.x * blockDim.x + threadIdx.x;
    for (int i = idx; i < G4 * HS; i += stride) {
        int n = i >> 9, k = i & (HS - 1);
        float v = Wh[(size_t)k * G4 + (n & 3) * HS + (n >> 2)];
        BF h = __float2bfloat16(v);
        g_WhHi[i] = h; g_WhLo[i] = __float2bfloat16(v - __bfloat162float(h));
    }
    for (int i = idx; i < G4 * HIDD; i += stride) {
        int n = i >> 8, k = i & (HIDD - 1);
        float v = Wi[(size_t)k * G4 + (n & 3) * HS + (n >> 2)];
        BF h = __float2bfloat16(v);
        g_WiHi[i] = h; g_WiLo[i] = __float2bfloat16(v - __bfloat162float(h));
    }
    for (int i = idx; i < G4; i += stride)
        g_bP[i] = bl[(i & 3) * HS + (i >> 2)];
    if (idx < 16 * 32) g_flag[idx] = 0;
}

// ---------------- encoder ----------------
__global__ void __launch_bounds__(256) enc_kernel(const float* __restrict__ A,
                                                  const float* __restrict__ B,
                                                  const float* __restrict__ bias) {
    __shared__ float As[64 * 68];
    __shared__ float Bs[64 * 64];
    int nb = blockIdx.x, mb = blockIdx.y, tid = threadIdx.x;
    int tn = tid & 15, tm = tid >> 4;
    float acc[4][4];
#pragma unroll
    for (int i = 0; i < 4; i++)
#pragma unroll
        for (int j = 0; j < 4; j++) acc[i][j] = 0.f;
    for (int kc = 0; kc < 2; kc++) {
        __syncthreads();
#pragma unroll
        for (int p = 0; p < 4; p++) {
            int idx = p * 256 + tid, r = idx >> 4, c4 = (idx & 15) << 2;
            *(float4*)&As[r * 68 + c4] = *(const float4*)&A[(size_t)(mb * 64 + r) * OBSD + kc * 64 + c4];
            *(float4*)&Bs[r * 64 + c4] = *(const float4*)&B[(size_t)(kc * 64 + r) * HIDD + nb * 64 + c4];
        }
        __syncthreads();
#pragma unroll 8
        for (int kk = 0; kk < 64; kk++) {
            float4 w = *(const float4*)&Bs[kk * 64 + tn * 4];
#pragma unroll
            for (int i = 0; i < 4; i++) {
                float a = As[(tm * 4 + i) * 68 + kk];
                acc[i][0] += a * w.x; acc[i][1] += a * w.y;
                acc[i][2] += a * w.z; acc[i][3] += a * w.w;
            }
        }
    }
    int n0 = nb * 64 + tn * 4;
    float4 bb = *(const float4*)&bias[n0];
#pragma unroll
    for (int i = 0; i < 4; i++) {
        int row = mb * 64 + tm * 4 + i;
        float v[4] = { geluf(acc[i][0] + bb.x), geluf(acc[i][1] + bb.y),
                       geluf(acc[i][2] + bb.z), geluf(acc[i][3] + bb.w) };
        __align__(8) BF hb[4], lb[4];
#pragma unroll
        for (int q = 0; q < 4; q++) {
            hb[q] = __float2bfloat16(v[q]);
            lb[q] = __float2bfloat16(v[q] - __bfloat162float(hb[q]));
        }
        *(int2*)(g_fHi + (size_t)row * HIDD + n0) = *(int2*)hb;
        *(int2*)(g_fLo + (size_t)row * HIDD + n0) = *(int2*)lb;
    }
}

// ---------------- x_gates (bf16-split HMMA, n-split x k-split warps) ----------------
__global__ void __launch_bounds__(256) xg_mma_kernel() {
    extern __shared__ char sm[];
    uint32_t sb = smem_u32(sm);
    int tid = threadIdx.x, lane = tid & 31, wid = tid >> 5;
    int nb = blockIdx.x, my = blockIdx.y;
    int ng = wid & 1, kg = wid >> 1;

    {
        BF* Whi = (BF*)(sm + X_W_HI);
        BF* Wlo = (BF*)(sm + X_W_LO);
        const BF* sh = g_WiHi + (size_t)(nb * 64) * HIDD;
        const BF* sl = g_WiLo + (size_t)(nb * 64) * HIDD;
        for (int i = tid; i < 2048; i += 256) {
            int r = i >> 5, c8 = (i & 31) * 8;
            *(int4*)&Whi[r * WST_X + c8] = *(const int4*)&sh[(size_t)r * HIDD + c8];
            *(int4*)&Wlo[r * WST_X + c8] = *(const int4*)&sl[(size_t)r * HIDD + c8];
        }
    }
    float acc[4][4][4];
#pragma unroll
    for (int a = 0; a < 4; a++)
#pragma unroll
        for (int b = 0; b < 4; b++)
#pragma unroll
            for (int e = 0; e < 4; e++) acc[a][b][e] = 0.f;

    const BF* Ah = g_fHi + (size_t)(my * 64) * HIDD;
    const BF* Al = g_fLo + (size_t)(my * 64) * HIDD;
    const uint32_t bufs[2] = { sb + X_BUF0, sb + X_BUF1 };

    stage_cp(bufs[0], bufs[0] + CHUNK_BYTES, Ah, Al, HIDD, tid);
    CP_COMMIT();
#pragma unroll
    for (int ch = 0; ch < 2; ch++) {
        CP_WAIT0();
        __syncthreads();
        if (ch < 1) {
            stage_cp(bufs[1], bufs[1] + CHUNK_BYTES, Ah + 128, Al + 128, HIDD, tid);
            CP_COMMIT();
        }
        mma_2ks(bufs[ch], bufs[ch] + CHUNK_BYTES, sb + X_W_HI, sb + X_W_LO,
                WST_X, kg, ch * 8, ng, lane, acc);
    }
    __syncthreads();
    float* part = (float*)(sm + X_PART);
    sts_part(part, acc, kg, ng, lane);
    __syncthreads();

    int erow = tid >> 2, eu4 = tid & 3;
    int col0 = nb * 64 + eu4 * 16;
    float* op = g_xgp + ((size_t)my * 64 + erow) * G4 + col0;
#pragma unroll
    for (int j = 0; j < 16; j += 4) {
        float4 v = *(const float4*)&part[(0 * 64 + erow) * 68 + eu4 * 16 + j];
#pragma unroll
        for (int k = 1; k < 4; k++) {
            float4 p = *(const float4*)&part[(k * 64 + erow) * 68 + eu4 * 16 + j];
            v.x += p.x; v.y += p.y; v.z += p.z; v.w += p.w;
        }
        float4 bb = *(const float4*)&g_bP[col0 + j];
        v.x += bb.x; v.y += bb.y; v.z += bb.z; v.w += bb.w;
        *(float4*)(op + j) = v;
    }
}

// ---------------- persistent HMMA LSTM scan (fine-grained chunk flags) ----------------
// 128 CTAs = 4 mb(64 batch) x 32 nb(64 gate cols). 8 warps = 2 n-groups x 4 k-groups.
// Producer of its 16 h-columns arrives on g_flag[mb][nb>>3] after storing h(t);
// consumer acquire-polls only the 8-producer flag of the chunk it stages next.
__global__ void __launch_bounds__(256) scan_mma_kernel() {
    extern __shared__ char sm[];
    uint32_t sb = smem_u32(sm);
    float* cS = (float*)(sm + S_CS);
    float* part = (float*)(sm + S_PART);
    int tid = threadIdx.x, lane = tid & 31, wid = tid >> 5;
    int mb = blockIdx.x >> 5, nb = blockIdx.x & 31;
    int ng = wid & 1, kg = wid >> 1;
    unsigned* myflag = &g_flag[(mb * 4 + (nb >> 3)) * 32];
    unsigned* base = &g_flag[mb * 4 * 32];

    {
        BF* Whi = (BF*)(sm + S_W_HI);
        BF* Wlo = (BF*)(sm + S_W_LO);
        const BF* sh = g_WhHi + (size_t)(nb * 64) * HS;
        const BF* sl = g_WhLo + (size_t)(nb * 64) * HS;
        for (int i = tid; i < 4096; i += 256) {
            int r = i >> 6, c8 = (i & 63) * 8;
            *(int4*)&Whi[r * WST_S + c8] = *(const int4*)&sh[(size_t)r * HS + c8];
            *(int4*)&Wlo[r * WST_S + c8] = *(const int4*)&sl[(size_t)r * HS + c8];
        }
    }
    for (int i = tid; i < 64 * 16; i += 256) cS[i] = 0.f;
    __syncthreads();

    int erow = tid >> 2, eu4 = tid & 3;
    const uint32_t bufs[2] = { sb + S_BUF0, sb + S_BUF1 };

#pragma unroll 1
    for (int t = 0; t < T_STEPS; t++) {
        // prefetch this thread's gate inputs (overlaps polls / cp.async)
        const float* xgp = g_xgp + ((size_t)t * BATCH + mb * 64 + erow) * G4 + nb * 64 + eu4 * 16;
        float xr[16];
        *(float4*)&xr[0]  = *(const float4*)(xgp + 0);
        *(float4*)&xr[4]  = *(const float4*)(xgp + 4);
        *(float4*)&xr[8]  = *(const float4*)(xgp + 8);
        *(float4*)&xr[12] = *(const float4*)(xgp + 12);

        if (t > 0) {
            float acc[4][4][4];
#pragma unroll
            for (int a = 0; a < 4; a++)
#pragma unroll
                for (int b = 0; b < 4; b++)
#pragma unroll
                    for (int e = 0; e < 4; e++) acc[a][b][e] = 0.f;

            const BF* Ah = g_hHi + ((size_t)(t - 1) * BATCH + mb * 64) * HS;
            const BF* Al = g_hLo + ((size_t)(t - 1) * BATCH + mb * 64) * HS;
            unsigned target = (unsigned)t * 8u;

            // chunk0: wait for its 8 producers only
            if (tid == 0) flag_spin(base + 0 * 32, target);
            __syncthreads();
            stage_cp(bufs[0], bufs[0] + CHUNK_BYTES, Ah, Al, HS, tid);
            CP_COMMIT();
#pragma unroll 1
            for (int ch = 0; ch < 4; ch++) {
                if (ch < 3 && tid == 0) flag_spin(base + (ch + 1) * 32, target);
                CP_WAIT0();
                __syncthreads();
                if (ch < 3) {
                    uint32_t nbuf = bufs[(ch + 1) & 1];
                    stage_cp(nbuf, nbuf + CHUNK_BYTES,
                             Ah + (ch + 1) * 128, Al + (ch + 1) * 128, HS, tid);
                    CP_COMMIT();
                }
                mma_2ks(bufs[ch & 1], bufs[ch & 1] + CHUNK_BYTES,
                        sb + S_W_HI, sb + S_W_LO, WST_S, kg, ch * 8, ng, lane, acc);
            }
            __syncthreads();              // A buffers dead -> safe to alias part
            sts_part(part, acc, kg, ng, lane);
        }
        __syncthreads();

        // epilogue: 4 units per thread, c in SMEM (thread-exclusive slot)
        float g[16];
#pragma unroll
        for (int j = 0; j < 16; j += 4) *(float4*)&g[j] = make_float4(0.f, 0.f, 0.f, 0.f);
        if (t > 0) {
#pragma unroll
            for (int k = 0; k < 4; k++)
#pragma unroll
                for (int j = 0; j < 16; j += 4) {
                    float4 p = *(const float4*)&part[(k * 64 + erow) * 68 + eu4 * 16 + j];
                    g[j] += p.x; g[j + 1] += p.y; g[j + 2] += p.z; g[j + 3] += p.w;
                }
        }
        float* cp = &cS[erow * 16 + eu4 * 4];
        __align__(8) BF hb[4], lb[4];
#pragma unroll
        for (int q = 0; q < 4; q++) {
            float zi = g[q * 4 + 0] + xr[q * 4 + 0];
            float zf = g[q * 4 + 1] + xr[q * 4 + 1];
            float zg = g[q * 4 + 2] + xr[q * 4 + 2];
            float zo = g[q * 4 + 3] + xr[q * 4 + 3];
            float cn = sigmf(zf) * cp[q] + sigmf(zi) * tanhf(zg);
            cp[q] = cn;
            float hv = sigmf(zo) * tanhf(cn);
            BF hh = __float2bfloat16(hv);
            hb[q] = hh;
            lb[q] = __float2bfloat16(hv - __bfloat162float(hh));
        }
        size_t ho = ((size_t)t * BATCH + mb * 64 + erow) * HS + nb * 16 + eu4 * 4;
        *(int2*)&g_hHi[ho] = *(int2*)hb;
        *(int2*)&g_hLo[ho] = *(int2*)lb;

        // release this CTA's h(t) slice (stores -> bar -> release-red)
        __syncthreads();
        if (tid == 0) flag_arrive(myflag);
    }
}

// ---------------- heads ----------------
__global__ void __launch_bounds__(256) heads_kernel(
    const float* __restrict__ Wmu, const float* __restrict__ bmu,
    const float* __restrict__ lstd, const float* __restrict__ Wv,
    const float* __restrict__ bv, float* __restrict__ out) {
    __shared__ float Wt[17 * HS];
    __shared__ float sig_s[16], bias_s[17];
    int tid = threadIdx.x;
    for (int i = tid; i < HS * ACTD; i += 256) {
        int k = i >> 4, a = i & 15;
        Wt[a * HS + k] = Wmu[(size_t)k * ACTD + a];
    }
    for (int i = tid; i < HS; i += 256) Wt[16 * HS + i] = Wv[i];
    if (tid < 16) { sig_s[tid] = expf(lstd[tid]); bias_s[tid] = bmu[tid]; }
    if (tid == 16) bias_s[16] = bv[0];
    __syncthreads();

    int warp = tid >> 5, lane = tid & 31;
    int step = gridDim.x * 8;
    for (int row = blockIdx.x * 8 + warp; row < TBROWS; row += step) {
        const BF* hh = g_hHi + (size_t)row * HS;
        const BF* hl = g_hLo + (size_t)row * HS;
        float acc[17];
#pragma unroll
        for (int a = 0; a < 17; a++) acc[a] = 0.f;
#pragma unroll 4
        for (int q = 0; q < 16; q++) {
            int idx = q * 32 + lane;
            float hv = __bfloat162float(hh[idx]) + __bfloat162float(hl[idx]);
#pragma unroll
            for (int a = 0; a < 17; a++) acc[a] += hv * Wt[a * HS + idx];
        }
#pragma unroll
        for (int a = 0; a < 17; a++)
#pragma unroll
            for (int off = 16; off > 0; off >>= 1)
                acc[a] += __shfl_xor_sync(0xffffffffu, acc[a], off);
        if (lane < 16) {
            out[(size_t)row * ACTD + lane] = acc[lane] + bias_s[lane];
            out[(size_t)TBROWS * ACTD + (size_t)row * ACTD + lane] = sig_s[lane];
        }
        if (lane == 0)
            out[(size_t)TBROWS * ACTD * 2 + row] = acc[16] + bias_s[16];
    }
}

// ---------------- launch ----------------
extern "C" void kernel_launch(void* const* d_in, const int* in_sizes, int n_in,
                              void* d_out, int out_size) {
    const float* x     = (const float*)d_in[0];
    const float* W_enc = (const float*)d_in[1];
    const float* b_enc = (const float*)d_in[2];
    const float* Wi    = (const float*)d_in[3];
    const float* Wh    = (const float*)d_in[4];
    const float* b_l   = (const float*)d_in[5];
    const float* W_mu  = (const float*)d_in[6];
    const float* b_mu  = (const float*)d_in[7];
    const float* lstd  = (const float*)d_in[8];
    const float* W_v   = (const float*)d_in[9];
    const float* b_v   = (const float*)d_in[10];
    float* out = (float*)d_out;

    cudaFuncSetAttribute(xg_mma_kernel,   cudaFuncAttributeMaxDynamicSharedMemorySize, X_DYN);
    cudaFuncSetAttribute(scan_mma_kernel, cudaFuncAttributeMaxDynamicSharedMemorySize, S_DYN);

    prep_kernel<<<1024, 256>>>(Wi, Wh, b_l);
    enc_kernel<<<dim3(HIDD / 64, TBROWS / 64), 256>>>(x, W_enc, b_enc);
    xg_mma_kernel<<<dim3(32, TBROWS / 64), 256, X_DYN>>>();
    scan_mma_kernel<<<NCTA, 256, S_DYN>>>();
    heads_kernel<<<1024, 256>>>(W_mu, b_mu, lstd, W_v, b_v, out);
}

// round 11
// speedup vs baseline: 1.1018x; 1.1018x over previous
#include <cuda_runtime.h>
#include <cuda_bf16.h>
#include <math.h>
#include <stdint.h>

#define T_STEPS 256
#define BATCH   256
#define OBSD    128
#define HIDD    256
#define HS      512
#define G4      2048
#define ACTD    16
#define TBROWS  (T_STEPS * BATCH)
#define NCTA    128
typedef __nv_bfloat16 BF;

// ---------------- scratch (static device arrays; no cudaMalloc) ----------------
__device__ __align__(16) float g_xgp[(size_t)TBROWS * G4];
__device__ __align__(16) BF    g_fHi[(size_t)TBROWS * HIDD];
__device__ __align__(16) BF    g_fLo[(size_t)TBROWS * HIDD];
__device__ __align__(16) BF    g_hHi[(size_t)TBROWS * HS];
__device__ __align__(16) BF    g_hLo[(size_t)TBROWS * HS];
__device__ __align__(16) BF    g_WhHi[(size_t)G4 * HS];      // [n][k] permuted+transposed
__device__ __align__(16) BF    g_WhLo[(size_t)G4 * HS];
__device__ __align__(16) BF    g_WiHi[(size_t)G4 * HIDD];
__device__ __align__(16) BF    g_WiLo[(size_t)G4 * HIDD];
__device__ __align__(16) float g_bP[G4];
__device__ unsigned g_cnt;

__device__ __forceinline__ float sigmf(float x) { return 1.0f / (1.0f + expf(-x)); }
__device__ __forceinline__ float geluf(float v) {
    float u = 0.7978845608028654f * (v + 0.044715f * v * v * v);
    return 0.5f * v * (1.0f + tanhf(u));
}
__device__ __forceinline__ uint32_t smem_u32(const void* p) {
    uint32_t a;
    asm("{ .reg .u64 t; cvta.to.shared.u64 t, %1; cvt.u32.u64 %0, t; }" : "=r"(a) : "l"(p));
    return a;
}
__device__ __forceinline__ void ldmx4(uint32_t addr, uint32_t* r) {
    asm volatile("ldmatrix.sync.aligned.m8n8.x4.shared.b16 {%0,%1,%2,%3}, [%4];"
        : "=r"(r[0]), "=r"(r[1]), "=r"(r[2]), "=r"(r[3]) : "r"(addr));
}
__device__ __forceinline__ void mma16816(float* d, const uint32_t* a, const uint32_t* b) {
    asm volatile("mma.sync.aligned.m16n8k16.row.col.f32.bf16.bf16.f32 "
        "{%0,%1,%2,%3}, {%4,%5,%6,%7}, {%8,%9}, {%0,%1,%2,%3};"
        : "+f"(d[0]), "+f"(d[1]), "+f"(d[2]), "+f"(d[3])
        : "r"(a[0]), "r"(a[1]), "r"(a[2]), "r"(a[3]), "r"(b[0]), "r"(b[1]));
}
#define CP_COMMIT() asm volatile("cp.async.commit_group;" ::: "memory")
#define CP_WAIT0()  asm volatile("cp.async.wait_group 0;" ::: "memory")

// A stage stride: 136 elems (272B, ≡16 mod 128 -> conflict-free ldmatrix)
#define AST 136
#define CHUNK_BYTES 17408          // 64 x 136 bf16
// ---- scan SMEM map (bytes) ----
#define S_W_HI  0
#define S_W_LO  66560
#define S_BUF0  133120             // [hi 17408][lo 17408]
#define S_BUF1  167936
#define S_PART  133120             // alias over both A buffers
#define S_CS    202752             // cell state 64x16 fp32
#define S_DYN   206848
#define WST_S   520
// ---- x_gates SMEM map ----
#define X_W_HI  0
#define X_W_LO  33792
#define X_BUF0  67584
#define X_BUF1  102400
#define X_PART  67584
#define X_DYN   137216
#define WST_X   264

// cp.async one K=128 chunk (64 rows) of A hi/lo into stage buffer (512 threads)
__device__ __forceinline__ void stage_cp(uint32_t dHi, uint32_t dLo,
                                         const BF* sHi, const BF* sLo,
                                         int ld, int tid) {
#pragma unroll
    for (int p = 0; p < 2; p++) {
        int j = tid + p * 512;
        int r = j >> 4, cb = j & 15;
        const BF* sh = sHi + (size_t)r * ld + cb * 8;
        const BF* sl = sLo + (size_t)r * ld + cb * 8;
        uint32_t dh = dHi + r * 272 + cb * 16;
        uint32_t dl = dLo + r * 272 + cb * 16;
        asm volatile("cp.async.cg.shared.global [%0], [%1], 16;\n\t"
                     "cp.async.cg.shared.global [%2], [%3], 16;"
                     :: "r"(dh), "l"(sh), "r"(dl), "l"(sl));
    }
}

// Warp (ng in [0,4), kg in [0,4)): m64 x n16 tile, 2 ksteps of this chunk, 3 split passes.
__device__ __forceinline__ void mma_2ks(uint32_t aHi, uint32_t aLo,
                                        uint32_t wHi, uint32_t wLo, int wst,
                                        int kg, int gk0, int ng, int lane,
                                        float acc[4][2][4]) {
#pragma unroll
    for (int s = 0; s < 2; s++) {
        int lks = kg * 2 + s;
        int gks = gk0 + lks;
        uint32_t bh[4], bl[4];
        int nrow = ng * 16 + (lane & 7) + ((lane >> 4) << 3);
        int kcol = gks * 16 + ((lane >> 3) & 1) * 8;
        ldmx4(wHi + (nrow * wst + kcol) * 2, bh);
        ldmx4(wLo + (nrow * wst + kcol) * 2, bl);
#pragma unroll
        for (int mt = 0; mt < 4; mt++) {
            uint32_t ah[4], al[4];
            int row = mt * 16 + (lane & 15);
            int col = lks * 16 + ((lane >> 4) << 3);
            ldmx4(aHi + (row * AST + col) * 2, ah);
            ldmx4(aLo + (row * AST + col) * 2, al);
#pragma unroll
            for (int q = 0; q < 2; q++) {
                mma16816(acc[mt][q], ah, &bh[q * 2]);
                mma16816(acc[mt][q], ah, &bl[q * 2]);
                mma16816(acc[mt][q], al, &bh[q * 2]);
            }
        }
    }
}

// STS k-split partials: part[kg][row 64][col 64], stride 68 floats
__device__ __forceinline__ void sts_part(float* part, float acc[4][2][4],
                                         int kg, int ng, int lane) {
#pragma unroll
    for (int mt = 0; mt < 4; mt++)
#pragma unroll
        for (int nt = 0; nt < 2; nt++) {
            int row0 = mt * 16 + (lane >> 2);
            int col = ng * 16 + nt * 8 + (lane & 3) * 2;
            *(float2*)&part[(kg * 64 + row0) * 68 + col] = *(float2*)&acc[mt][nt][0];
            *(float2*)&part[(kg * 64 + row0 + 8) * 68 + col] = *(float2*)&acc[mt][nt][2];
        }
}

// ---------------- prep ----------------
__global__ void prep_kernel(const float* __restrict__ Wi, const float* __restrict__ Wh,
                            const float* __restrict__ bl) {
    int stride = gridDim.x * blockDim.x;
    int idx = blockIdx.x * blockDim.x + threadIdx.x;
    for (int i = idx; i < G4 * HS; i += stride) {
        int n = i >> 9, k = i & (HS - 1);
        float v = Wh[(size_t)k * G4 + (n & 3) * HS + (n >> 2)];
        BF h = __float2bfloat16(v);
        g_WhHi[i] = h; g_WhLo[i] = __float2bfloat16(v - __bfloat162float(h));
    }
    for (int i = idx; i < G4 * HIDD; i += stride) {
        int n = i >> 8, k = i & (HIDD - 1);
        float v = Wi[(size_t)k * G4 + (n & 3) * HS + (n >> 2)];
        BF h = __float2bfloat16(v);
        g_WiHi[i] = h; g_WiLo[i] = __float2bfloat16(v - __bfloat162float(h));
    }
    for (int i = idx; i < G4; i += stride)
        g_bP[i] = bl[(i & 3) * HS + (i >> 2)];
    if (idx == 0) g_cnt = 0;
}

// ---------------- encoder ----------------
__global__ void __launch_bounds__(256) enc_kernel(const float* __restrict__ A,
                                                  const float* __restrict__ B,
                                                  const float* __restrict__ bias) {
    __shared__ float As[64 * 68];
    __shared__ float Bs[64 * 64];
    int nb = blockIdx.x, mb = blockIdx.y, tid = threadIdx.x;
    int tn = tid & 15, tm = tid >> 4;
    float acc[4][4];
#pragma unroll
    for (int i = 0; i < 4; i++)
#pragma unroll
        for (int j = 0; j < 4; j++) acc[i][j] = 0.f;
    for (int kc = 0; kc < 2; kc++) {
        __syncthreads();
#pragma unroll
        for (int p = 0; p < 4; p++) {
            int idx = p * 256 + tid, r = idx >> 4, c4 = (idx & 15) << 2;
            *(float4*)&As[r * 68 + c4] = *(const float4*)&A[(size_t)(mb * 64 + r) * OBSD + kc * 64 + c4];
            *(float4*)&Bs[r * 64 + c4] = *(const float4*)&B[(size_t)(kc * 64 + r) * HIDD + nb * 64 + c4];
        }
        __syncthreads();
#pragma unroll 8
        for (int kk = 0; kk < 64; kk++) {
            float4 w = *(const float4*)&Bs[kk * 64 + tn * 4];
#pragma unroll
            for (int i = 0; i < 4; i++) {
                float a = As[(tm * 4 + i) * 68 + kk];
                acc[i][0] += a * w.x; acc[i][1] += a * w.y;
                acc[i][2] += a * w.z; acc[i][3] += a * w.w;
            }
        }
    }
    int n0 = nb * 64 + tn * 4;
    float4 bb = *(const float4*)&bias[n0];
#pragma unroll
    for (int i = 0; i < 4; i++) {
        int row = mb * 64 + tm * 4 + i;
        float v[4] = { geluf(acc[i][0] + bb.x), geluf(acc[i][1] + bb.y),
                       geluf(acc[i][2] + bb.z), geluf(acc[i][3] + bb.w) };
        __align__(8) BF hb[4], lb[4];
#pragma unroll
        for (int q = 0; q < 4; q++) {
            hb[q] = __float2bfloat16(v[q]);
            lb[q] = __float2bfloat16(v[q] - __bfloat162float(hb[q]));
        }
        *(int2*)(g_fHi + (size_t)row * HIDD + n0) = *(int2*)hb;
        *(int2*)(g_fLo + (size_t)row * HIDD + n0) = *(int2*)lb;
    }
}

// ---------------- x_gates (bf16-split HMMA, 512 threads, 4ng x 4kg) ----------------
__global__ void __launch_bounds__(512) xg_mma_kernel() {
    extern __shared__ char sm[];
    uint32_t sb = smem_u32(sm);
    int tid = threadIdx.x, lane = tid & 31, wid = tid >> 5;
    int nb = blockIdx.x, my = blockIdx.y;
    int ng = wid & 3, kg = wid >> 2;

    {
        BF* Whi = (BF*)(sm + X_W_HI);
        BF* Wlo = (BF*)(sm + X_W_LO);
        const BF* sh = g_WiHi + (size_t)(nb * 64) * HIDD;
        const BF* sl = g_WiLo + (size_t)(nb * 64) * HIDD;
        for (int i = tid; i < 2048; i += 512) {
            int r = i >> 5, c8 = (i & 31) * 8;
            *(int4*)&Whi[r * WST_X + c8] = *(const int4*)&sh[(size_t)r * HIDD + c8];
            *(int4*)&Wlo[r * WST_X + c8] = *(const int4*)&sl[(size_t)r * HIDD + c8];
        }
    }
    float acc[4][2][4];
#pragma unroll
    for (int a = 0; a < 4; a++)
#pragma unroll
        for (int b = 0; b < 2; b++)
#pragma unroll
            for (int e = 0; e < 4; e++) acc[a][b][e] = 0.f;

    const BF* Ah = g_fHi + (size_t)(my * 64) * HIDD;
    const BF* Al = g_fLo + (size_t)(my * 64) * HIDD;
    const uint32_t bufs[2] = { sb + X_BUF0, sb + X_BUF1 };

    stage_cp(bufs[0], bufs[0] + CHUNK_BYTES, Ah, Al, HIDD, tid);
    CP_COMMIT();
#pragma unroll
    for (int ch = 0; ch < 2; ch++) {
        CP_WAIT0();
        __syncthreads();
        if (ch < 1) {
            stage_cp(bufs[1], bufs[1] + CHUNK_BYTES, Ah + 128, Al + 128, HIDD, tid);
            CP_COMMIT();
        }
        mma_2ks(bufs[ch], bufs[ch] + CHUNK_BYTES, sb + X_W_HI, sb + X_W_LO,
                WST_X, kg, ch * 8, ng, lane, acc);
    }
    __syncthreads();
    float* part = (float*)(sm + X_PART);
    sts_part(part, acc, kg, ng, lane);
    __syncthreads();

    int erow = tid >> 3, eu = tid & 7;             // 8 gate cols per thread
    int col0 = nb * 64 + eu * 8;
    float* op = g_xgp + ((size_t)my * 64 + erow) * G4 + col0;
#pragma unroll
    for (int j = 0; j < 8; j += 4) {
        float4 v = *(const float4*)&part[(0 * 64 + erow) * 68 + eu * 8 + j];
#pragma unroll
        for (int k = 1; k < 4; k++) {
            float4 p = *(const float4*)&part[(k * 64 + erow) * 68 + eu * 8 + j];
            v.x += p.x; v.y += p.y; v.z += p.z; v.w += p.w;
        }
        float4 bb = *(const float4*)&g_bP[col0 + j];
        v.x += bb.x; v.y += bb.y; v.z += bb.z; v.w += bb.w;
        *(float4*)(op + j) = v;
    }
}

// ---------------- persistent HMMA LSTM scan (512 threads, 4ng x 4kg) ----------------
// 128 CTAs = 4 mb(64 batch) x 32 nb(64 gate cols). 16 warps = 4 n-groups x 4 k-groups.
__global__ void __launch_bounds__(512) scan_mma_kernel() {
    extern __shared__ char sm[];
    uint32_t sb = smem_u32(sm);
    float* cS = (float*)(sm + S_CS);
    float* part = (float*)(sm + S_PART);
    int tid = threadIdx.x, lane = tid & 31, wid = tid >> 5;
    int mb = blockIdx.x >> 5, nb = blockIdx.x & 31;
    int ng = wid & 3, kg = wid >> 2;

    {
        BF* Whi = (BF*)(sm + S_W_HI);
        BF* Wlo = (BF*)(sm + S_W_LO);
        const BF* sh = g_WhHi + (size_t)(nb * 64) * HS;
        const BF* sl = g_WhLo + (size_t)(nb * 64) * HS;
        for (int i = tid; i < 4096; i += 512) {
            int r = i >> 6, c8 = (i & 63) * 8;
            *(int4*)&Whi[r * WST_S + c8] = *(const int4*)&sh[(size_t)r * HS + c8];
            *(int4*)&Wlo[r * WST_S + c8] = *(const int4*)&sl[(size_t)r * HS + c8];
        }
    }
    for (int i = tid; i < 64 * 16; i += 512) cS[i] = 0.f;
    __syncthreads();

    int erow = tid >> 3, eu = tid & 7;             // 8 gate cols = 2 units per thread
    const uint32_t bufs[2] = { sb + S_BUF0, sb + S_BUF1 };

#pragma unroll 1
    for (int t = 0; t < T_STEPS; t++) {
        // prefetch this thread's gate inputs (overlaps staging / MMA)
        const float* xgp = g_xgp + ((size_t)t * BATCH + mb * 64 + erow) * G4 + nb * 64 + eu * 8;
        float xr[8];
        *(float4*)&xr[0] = *(const float4*)(xgp + 0);
        *(float4*)&xr[4] = *(const float4*)(xgp + 4);

        if (t > 0) {
            float acc[4][2][4];
#pragma unroll
            for (int a = 0; a < 4; a++)
#pragma unroll
                for (int b = 0; b < 2; b++)
#pragma unroll
                    for (int e = 0; e < 4; e++) acc[a][b][e] = 0.f;

            const BF* Ah = g_hHi + ((size_t)(t - 1) * BATCH + mb * 64) * HS;
            const BF* Al = g_hLo + ((size_t)(t - 1) * BATCH + mb * 64) * HS;

            stage_cp(bufs[0], bufs[0] + CHUNK_BYTES, Ah, Al, HS, tid);
            CP_COMMIT();
#pragma unroll 1
            for (int ch = 0; ch < 4; ch++) {
                CP_WAIT0();
                __syncthreads();
                if (ch < 3) {
                    uint32_t nbuf = bufs[(ch + 1) & 1];
                    stage_cp(nbuf, nbuf + CHUNK_BYTES,
                             Ah + (ch + 1) * 128, Al + (ch + 1) * 128, HS, tid);
                    CP_COMMIT();
                }
                mma_2ks(bufs[ch & 1], bufs[ch & 1] + CHUNK_BYTES,
                        sb + S_W_HI, sb + S_W_LO, WST_S, kg, ch * 8, ng, lane, acc);
            }
            __syncthreads();              // A buffers dead -> safe to alias part
            sts_part(part, acc, kg, ng, lane);
        }
        __syncthreads();

        // epilogue: 2 units per thread, c in SMEM (thread-exclusive slot)
        float g[8];
#pragma unroll
        for (int j = 0; j < 8; j++) g[j] = 0.f;
        if (t > 0) {
#pragma unroll
            for (int k = 0; k < 4; k++)
#pragma unroll
                for (int j = 0; j < 8; j += 4) {
                    float4 p = *(const float4*)&part[(k * 64 + erow) * 68 + eu * 8 + j];
                    g[j] += p.x; g[j + 1] += p.y; g[j + 2] += p.z; g[j + 3] += p.w;
                }
        }
        float* cp = &cS[erow * 16 + eu * 2];
        __align__(4) BF hb[2], lb[2];
#pragma unroll
        for (int q = 0; q < 2; q++) {
            float zi = g[q * 4 + 0] + xr[q * 4 + 0];
            float zf = g[q * 4 + 1] + xr[q * 4 + 1];
            float zg = g[q * 4 + 2] + xr[q * 4 + 2];
            float zo = g[q * 4 + 3] + xr[q * 4 + 3];
            float cn = sigmf(zf) * cp[q] + sigmf(zi) * tanhf(zg);
            cp[q] = cn;
            float hv = sigmf(zo) * tanhf(cn);
            BF hh = __float2bfloat16(hv);
            hb[q] = hh;
            lb[q] = __float2bfloat16(hv - __bfloat162float(hh));
        }
        size_t ho = ((size_t)t * BATCH + mb * 64 + erow) * HS + nb * 16 + eu * 2;
        *(uint32_t*)&g_hHi[ho] = *(uint32_t*)hb;
        *(uint32_t*)&g_hLo[ho] = *(uint32_t*)lb;

        // grid barrier (release h(t); all 128 CTAs single-wave)
        __syncthreads();
        if (tid == 0) {
            __threadfence();
            atomicAdd(&g_cnt, 1u);
            unsigned target = (unsigned)(t + 1) * NCTA, v;
            do {
                asm volatile("ld.acquire.gpu.u32 %0, [%1];" : "=r"(v) : "l"(&g_cnt) : "memory");
            } while (v < target);
        }
        __syncthreads();
    }
}

// ---------------- heads ----------------
__global__ void __launch_bounds__(256) heads_kernel(
    const float* __restrict__ Wmu, const float* __restrict__ bmu,
    const float* __restrict__ lstd, const float* __restrict__ Wv,
    const float* __restrict__ bv, float* __restrict__ out) {
    __shared__ float Wt[17 * HS];
    __shared__ float sig_s[16], bias_s[17];
    int tid = threadIdx.x;
    for (int i = tid; i < HS * ACTD; i += 256) {
        int k = i >> 4, a = i & 15;
        Wt[a * HS + k] = Wmu[(size_t)k * ACTD + a];
    }
    for (int i = tid; i < HS; i += 256) Wt[16 * HS + i] = Wv[i];
    if (tid < 16) { sig_s[tid] = expf(lstd[tid]); bias_s[tid] = bmu[tid]; }
    if (tid == 16) bias_s[16] = bv[0];
    __syncthreads();

    int warp = tid >> 5, lane = tid & 31;
    int step = gridDim.x * 8;
    for (int row = blockIdx.x * 8 + warp; row < TBROWS; row += step) {
        const BF* hh = g_hHi + (size_t)row * HS;
        const BF* hl = g_hLo + (size_t)row * HS;
        float acc[17];
#pragma unroll
        for (int a = 0; a < 17; a++) acc[a] = 0.f;
#pragma unroll 4
        for (int q = 0; q < 16; q++) {
            int idx = q * 32 + lane;
            float hv = __bfloat162float(hh[idx]) + __bfloat162float(hl[idx]);
#pragma unroll
            for (int a = 0; a < 17; a++) acc[a] += hv * Wt[a * HS + idx];
        }
#pragma unroll
        for (int a = 0; a < 17; a++)
#pragma unroll
            for (int off = 16; off > 0; off >>= 1)
                acc[a] += __shfl_xor_sync(0xffffffffu, acc[a], off);
        if (lane < 16) {
            out[(size_t)row * ACTD + lane] = acc[lane] + bias_s[lane];
            out[(size_t)TBROWS * ACTD + (size_t)row * ACTD + lane] = sig_s[lane];
        }
        if (lane == 0)
            out[(size_t)TBROWS * ACTD * 2 + row] = acc[16] + bias_s[16];
    }
}

// ---------------- launch ----------------
extern "C" void kernel_launch(void* const* d_in, const int* in_sizes, int n_in,
                              void* d_out, int out_size) {
    const float* x     = (const float*)d_in[0];
    const float* W_enc = (const float*)d_in[1];
    const float* b_enc = (const float*)d_in[2];
    const float* Wi    = (const float*)d_in[3];
    const float* Wh    = (const float*)d_in[4];
    const float* b_l   = (const float*)d_in[5];
    const float* W_mu  = (const float*)d_in[6];
    const float* b_mu  = (const float*)d_in[7];
    const float* lstd  = (const float*)d_in[8];
    const float* W_v   = (const float*)d_in[9];
    const float* b_v   = (const float*)d_in[10];
    float* out = (float*)d_out;

    cudaFuncSetAttribute(xg_mma_kernel,   cudaFuncAttributeMaxDynamicSharedMemorySize, X_DYN);
    cudaFuncSetAttribute(scan_mma_kernel, cudaFuncAttributeMaxDynamicSharedMemorySize, S_DYN);

    prep_kernel<<<1024, 256>>>(Wi, Wh, b_l);
    enc_kernel<<<dim3(HIDD / 64, TBROWS / 64), 256>>>(x, W_enc, b_enc);
    xg_mma_kernel<<<dim3(32, TBROWS / 64), 512, X_DYN>>>();
    scan_mma_kernel<<<NCTA, 512, S_DYN>>>();
    heads_kernel<<<1024, 256>>>(W_mu, b_mu, lstd, W_v, b_v, out);
}

// round 12
// speedup vs baseline: 1.5287x; 1.3875x over previous
#include <cuda_runtime.h>
#include <cuda_fp16.h>
#include <math.h>
#include <stdint.h>

#define T_STEPS 256
#define BATCH   256
#define OBSD    128
#define HIDD    256
#define HS      512
#define G4      2048
#define ACTD    16
#define TBROWS  (T_STEPS * BATCH)
#define NCTA    128
typedef __half HF;

// ---------------- scratch (static device arrays; no cudaMalloc) ----------------
__device__ __align__(16) float g_xgp[(size_t)TBROWS * G4];
__device__ __align__(16) HF    g_fH[(size_t)TBROWS * HIDD];   // feats fp16
__device__ __align__(16) HF    g_hH[(size_t)TBROWS * HS];     // h fp16
__device__ __align__(16) HF    g_WhHi[(size_t)G4 * HS];       // [n][k] permuted+transposed
__device__ __align__(16) HF    g_WhLo[(size_t)G4 * HS];
__device__ __align__(16) HF    g_WiHi[(size_t)G4 * HIDD];
__device__ __align__(16) HF    g_WiLo[(size_t)G4 * HIDD];
__device__ __align__(16) float g_bP[G4];
__device__ __align__(128) unsigned g_cntA[128];               // per-mb barrier counters (mb*32)

__device__ __forceinline__ float sigmf(float x) { return 1.0f / (1.0f + expf(-x)); }
__device__ __forceinline__ float geluf(float v) {
    float u = 0.7978845608028654f * (v + 0.044715f * v * v * v);
    return 0.5f * v * (1.0f + tanhf(u));
}
__device__ __forceinline__ uint32_t smem_u32(const void* p) {
    uint32_t a;
    asm("{ .reg .u64 t; cvta.to.shared.u64 t, %1; cvt.u32.u64 %0, t; }" : "=r"(a) : "l"(p));
    return a;
}
__device__ __forceinline__ void ldmx4(uint32_t addr, uint32_t* r) {
    asm volatile("ldmatrix.sync.aligned.m8n8.x4.shared.b16 {%0,%1,%2,%3}, [%4];"
        : "=r"(r[0]), "=r"(r[1]), "=r"(r[2]), "=r"(r[3]) : "r"(addr));
}
__device__ __forceinline__ void mma16816(float* d, const uint32_t* a, const uint32_t* b) {
    asm volatile("mma.sync.aligned.m16n8k16.row.col.f32.f16.f16.f32 "
        "{%0,%1,%2,%3}, {%4,%5,%6,%7}, {%8,%9}, {%0,%1,%2,%3};"
        : "+f"(d[0]), "+f"(d[1]), "+f"(d[2]), "+f"(d[3])
        : "r"(a[0]), "r"(a[1]), "r"(a[2]), "r"(a[3]), "r"(b[0]), "r"(b[1]));
}
#define CP_COMMIT() asm volatile("cp.async.commit_group;" ::: "memory")
#define CP_WAIT0()  asm volatile("cp.async.wait_group 0;" ::: "memory")
__device__ __forceinline__ void flag_arrive(unsigned* f) {
    asm volatile("red.release.gpu.global.add.u32 [%0], %1;" :: "l"(f), "r"(1u) : "memory");
}
__device__ __forceinline__ void flag_spin(const unsigned* f, unsigned target) {
    unsigned v;
    do {
        asm volatile("ld.acquire.gpu.global.u32 %0, [%1];" : "=r"(v) : "l"(f) : "memory");
    } while (v < target);
}

// A stage stride: 136 halves (272B, ≡16 mod 128 -> conflict-free ldmatrix)
#define AST 136
#define CHUNK_BYTES 17408          // 64 x 136 halves
// ---- scan SMEM map (bytes) ----
#define S_W_HI  0
#define S_W_LO  66560
#define S_BUF0  133120             // A hi only, 17408 each
#define S_BUF1  150528
#define S_PART  133120             // part[4][32][68] f32 = 34816 -> aliases both A bufs
#define S_CS    167936             // cell state 64x16 fp32
#define S_DYN   172032
#define WST_S   520
// ---- x_gates SMEM map ----
#define X_W_HI  0
#define X_W_LO  33792
#define X_BUF0  67584
#define X_BUF1  84992
#define X_PART  67584              // aliases both A bufs (34816)
#define X_DYN   102400
#define WST_X   264

// cp.async one K=128 chunk (64 rows) of A (fp16, hi only) into stage buffer (512 thr)
__device__ __forceinline__ void stage_cp(uint32_t dst, const HF* src, int ld, int tid) {
#pragma unroll
    for (int p = 0; p < 2; p++) {
        int j = tid + p * 512;
        int r = j >> 4, cb = j & 15;
        const HF* s = src + (size_t)r * ld + cb * 8;
        uint32_t d = dst + r * 272 + cb * 16;
        asm volatile("cp.async.cg.shared.global [%0], [%1], 16;" :: "r"(d), "l"(s));
    }
}

// Warp (ng in [0,4), kg in [0,4)): m64 x n16 tile, 2 ksteps of this chunk, 2 passes.
__device__ __forceinline__ void mma_2ks(uint32_t aHi,
                                        uint32_t wHi, uint32_t wLo, int wst,
                                        int kg, int gk0, int ng, int lane,
                                        float acc[4][2][4]) {
#pragma unroll
    for (int s = 0; s < 2; s++) {
        int lks = kg * 2 + s;
        int gks = gk0 + lks;
        uint32_t bh[4], bl[4];
        int nrow = ng * 16 + (lane & 7) + ((lane >> 4) << 3);
        int kcol = gks * 16 + ((lane >> 3) & 1) * 8;
        ldmx4(wHi + (nrow * wst + kcol) * 2, bh);
        ldmx4(wLo + (nrow * wst + kcol) * 2, bl);
#pragma unroll
        for (int mt = 0; mt < 4; mt++) {
            uint32_t ah[4];
            int row = mt * 16 + (lane & 15);
            int col = lks * 16 + ((lane >> 4) << 3);
            ldmx4(aHi + (row * AST + col) * 2, ah);
#pragma unroll
            for (int q = 0; q < 2; q++) {
                mma16816(acc[mt][q], ah, &bh[q * 2]);
                mma16816(acc[mt][q], ah, &bl[q * 2]);
            }
        }
    }
}

// STS k-split partials for round r (rows [32r, 32r+32)): part[kg][32][68]
__device__ __forceinline__ void sts_part(float* part, float acc[4][2][4],
                                         int r, int kg, int ng, int lane) {
#pragma unroll
    for (int mt2 = 0; mt2 < 2; mt2++) {
        int mt = r * 2 + mt2;
#pragma unroll
        for (int nt = 0; nt < 2; nt++) {
            int row0 = mt2 * 16 + (lane >> 2);
            int col = ng * 16 + nt * 8 + (lane & 3) * 2;
            *(float2*)&part[(kg * 32 + row0) * 68 + col] = *(float2*)&acc[mt][nt][0];
            *(float2*)&part[(kg * 32 + row0 + 8) * 68 + col] = *(float2*)&acc[mt][nt][2];
        }
    }
}

// ---------------- prep: permuted+transposed fp16-split weights ----------------
__global__ void prep_kernel(const float* __restrict__ Wi, const float* __restrict__ Wh,
                            const float* __restrict__ bl) {
    int stride = gridDim.x * blockDim.x;
    int idx = blockIdx.x * blockDim.x + threadIdx.x;
    for (int i = idx; i < G4 * HS; i += stride) {
        int n = i >> 9, k = i & (HS - 1);
        float v = Wh[(size_t)k * G4 + (n & 3) * HS + (n >> 2)];
        HF h = __float2half(v);
        g_WhHi[i] = h; g_WhLo[i] = __float2half(v - __half2float(h));
    }
    for (int i = idx; i < G4 * HIDD; i += stride) {
        int n = i >> 8, k = i & (HIDD - 1);
        float v = Wi[(size_t)k * G4 + (n & 3) * HS + (n >> 2)];
        HF h = __float2half(v);
        g_WiHi[i] = h; g_WiLo[i] = __float2half(v - __half2float(h));
    }
    for (int i = idx; i < G4; i += stride)
        g_bP[i] = bl[(i & 3) * HS + (i >> 2)];
    if (idx < 128) g_cntA[idx] = 0;
}

// ---------------- encoder: feats = gelu(x@W_enc + b) -> fp16 ----------------
__global__ void __launch_bounds__(256) enc_kernel(const float* __restrict__ A,
                                                  const float* __restrict__ B,
                                                  const float* __restrict__ bias) {
    __shared__ float As[64 * 68];
    __shared__ float Bs[64 * 64];
    int nb = blockIdx.x, mb = blockIdx.y, tid = threadIdx.x;
    int tn = tid & 15, tm = tid >> 4;
    float acc[4][4];
#pragma unroll
    for (int i = 0; i < 4; i++)
#pragma unroll
        for (int j = 0; j < 4; j++) acc[i][j] = 0.f;
    for (int kc = 0; kc < 2; kc++) {
        __syncthreads();
#pragma unroll
        for (int p = 0; p < 4; p++) {
            int idx = p * 256 + tid, r = idx >> 4, c4 = (idx & 15) << 2;
            *(float4*)&As[r * 68 + c4] = *(const float4*)&A[(size_t)(mb * 64 + r) * OBSD + kc * 64 + c4];
            *(float4*)&Bs[r * 64 + c4] = *(const float4*)&B[(size_t)(kc * 64 + r) * HIDD + nb * 64 + c4];
        }
        __syncthreads();
#pragma unroll 8
        for (int kk = 0; kk < 64; kk++) {
            float4 w = *(const float4*)&Bs[kk * 64 + tn * 4];
#pragma unroll
            for (int i = 0; i < 4; i++) {
                float a = As[(tm * 4 + i) * 68 + kk];
                acc[i][0] += a * w.x; acc[i][1] += a * w.y;
                acc[i][2] += a * w.z; acc[i][3] += a * w.w;
            }
        }
    }
    int n0 = nb * 64 + tn * 4;
    float4 bb = *(const float4*)&bias[n0];
#pragma unroll
    for (int i = 0; i < 4; i++) {
        int row = mb * 64 + tm * 4 + i;
        __align__(8) HF hb[4];
        hb[0] = __float2half(geluf(acc[i][0] + bb.x));
        hb[1] = __float2half(geluf(acc[i][1] + bb.y));
        hb[2] = __float2half(geluf(acc[i][2] + bb.z));
        hb[3] = __float2half(geluf(acc[i][3] + bb.w));
        *(int2*)(g_fH + (size_t)row * HIDD + n0) = *(int2*)hb;
    }
}

// ---------------- x_gates (fp16 2-pass HMMA, 512 threads, 2 CTAs/SM) ----------------
__global__ void __launch_bounds__(512, 2) xg_mma_kernel() {
    extern __shared__ char sm[];
    uint32_t sb = smem_u32(sm);
    int tid = threadIdx.x, lane = tid & 31, wid = tid >> 5;
    int nb = blockIdx.x, my = blockIdx.y;
    int ng = wid & 3, kg = wid >> 2;

    {
        HF* Whi = (HF*)(sm + X_W_HI);
        HF* Wlo = (HF*)(sm + X_W_LO);
        const HF* sh = g_WiHi + (size_t)(nb * 64) * HIDD;
        const HF* sl = g_WiLo + (size_t)(nb * 64) * HIDD;
        for (int i = tid; i < 2048; i += 512) {
            int r = i >> 5, c8 = (i & 31) * 8;
            *(int4*)&Whi[r * WST_X + c8] = *(const int4*)&sh[(size_t)r * HIDD + c8];
            *(int4*)&Wlo[r * WST_X + c8] = *(const int4*)&sl[(size_t)r * HIDD + c8];
        }
    }
    float acc[4][2][4];
#pragma unroll
    for (int a = 0; a < 4; a++)
#pragma unroll
        for (int b = 0; b < 2; b++)
#pragma unroll
            for (int e = 0; e < 4; e++) acc[a][b][e] = 0.f;

    const HF* Ah = g_fH + (size_t)(my * 64) * HIDD;
    const uint32_t bufs[2] = { sb + X_BUF0, sb + X_BUF1 };

    stage_cp(bufs[0], Ah, HIDD, tid);
    CP_COMMIT();
#pragma unroll
    for (int ch = 0; ch < 2; ch++) {
        CP_WAIT0();
        __syncthreads();
        if (ch < 1) {
            stage_cp(bufs[1], Ah + 128, HIDD, tid);
            CP_COMMIT();
        }
        mma_2ks(bufs[ch], sb + X_W_HI, sb + X_W_LO, WST_X, kg, ch * 8, ng, lane, acc);
    }
    __syncthreads();

    float* part = (float*)(sm + X_PART);
    int prow = tid >> 4, eu = tid & 15;
#pragma unroll
    for (int r = 0; r < 2; r++) {
        sts_part(part, acc, r, kg, ng, lane);
        __syncthreads();
        int row = my * 64 + r * 32 + prow;
        int col0 = nb * 64 + eu * 4;
        float4 v = *(const float4*)&part[(0 * 32 + prow) * 68 + eu * 4];
#pragma unroll
        for (int k = 1; k < 4; k++) {
            float4 p = *(const float4*)&part[(k * 32 + prow) * 68 + eu * 4];
            v.x += p.x; v.y += p.y; v.z += p.z; v.w += p.w;
        }
        float4 bb = *(const float4*)&g_bP[col0];
        v.x += bb.x; v.y += bb.y; v.z += bb.z; v.w += bb.w;
        *(float4*)(g_xgp + (size_t)row * G4 + col0) = v;
        __syncthreads();
    }
}

// ---------------- persistent fp16 HMMA LSTM scan ----------------
// 128 CTAs = 4 mb(64 batch) x 32 nb(64 gate cols). 16 warps = 4 ng x 4 kg.
// Per-mb barrier: CTA (mb,nb) only depends on h rows produced by CTAs with same mb.
__global__ void __launch_bounds__(512) scan_mma_kernel() {
    extern __shared__ char sm[];
    uint32_t sb = smem_u32(sm);
    float* cS = (float*)(sm + S_CS);
    float* part = (float*)(sm + S_PART);
    int tid = threadIdx.x, lane = tid & 31, wid = tid >> 5;
    int mb = blockIdx.x >> 5, nb = blockIdx.x & 31;
    int ng = wid & 3, kg = wid >> 2;
    unsigned* ctr = &g_cntA[mb * 32];

    {
        HF* Whi = (HF*)(sm + S_W_HI);
        HF* Wlo = (HF*)(sm + S_W_LO);
        const HF* sh = g_WhHi + (size_t)(nb * 64) * HS;
        const HF* sl = g_WhLo + (size_t)(nb * 64) * HS;
        for (int i = tid; i < 4096; i += 512) {
            int r = i >> 6, c8 = (i & 63) * 8;
            *(int4*)&Whi[r * WST_S + c8] = *(const int4*)&sh[(size_t)r * HS + c8];
            *(int4*)&Wlo[r * WST_S + c8] = *(const int4*)&sl[(size_t)r * HS + c8];
        }
    }
    for (int i = tid; i < 64 * 16; i += 512) cS[i] = 0.f;
    __syncthreads();

    int prow = tid >> 4, eu = tid & 15;    // epilogue: 1 unit per thread per round
    const uint32_t bufs[2] = { sb + S_BUF0, sb + S_BUF1 };

#pragma unroll 1
    for (int t = 0; t < T_STEPS; t++) {
        // prefetch this thread's gate inputs for both epilogue rounds
        const float* xg0 = g_xgp + ((size_t)t * BATCH + mb * 64 + prow) * G4 + nb * 64 + eu * 4;
        float4 xv0 = *(const float4*)xg0;
        float4 xv1 = *(const float4*)(xg0 + (size_t)32 * G4);

        float acc[4][2][4];
        if (t > 0) {
#pragma unroll
            for (int a = 0; a < 4; a++)
#pragma unroll
                for (int b = 0; b < 2; b++)
#pragma unroll
                    for (int e = 0; e < 4; e++) acc[a][b][e] = 0.f;

            const HF* Ah = g_hH + ((size_t)(t - 1) * BATCH + mb * 64) * HS;
            stage_cp(bufs[0], Ah, HS, tid);
            CP_COMMIT();
#pragma unroll 1
            for (int ch = 0; ch < 4; ch++) {
                CP_WAIT0();
                __syncthreads();
                if (ch < 3) {
                    stage_cp(bufs[(ch + 1) & 1], Ah + (ch + 1) * 128, HS, tid);
                    CP_COMMIT();
                }
                mma_2ks(bufs[ch & 1], sb + S_W_HI, sb + S_W_LO, WST_S,
                        kg, ch * 8, ng, lane, acc);
            }
            __syncthreads();              // all MMAs done; A bufs dead -> part alias safe
        }

        // two epilogue rounds of 32 rows each
#pragma unroll
        for (int r = 0; r < 2; r++) {
            if (t > 0) sts_part(part, acc, r, kg, ng, lane);
            __syncthreads();
            float g0 = 0.f, g1 = 0.f, g2 = 0.f, g3 = 0.f;
            if (t > 0) {
#pragma unroll
                for (int k = 0; k < 4; k++) {
                    float4 p = *(const float4*)&part[(k * 32 + prow) * 68 + eu * 4];
                    g0 += p.x; g1 += p.y; g2 += p.z; g3 += p.w;
                }
            }
            float4 xv = r ? xv1 : xv0;
            float zi = g0 + xv.x, zf = g1 + xv.y, zg = g2 + xv.z, zo = g3 + xv.w;
            int ci = (r * 32 + prow) * 16 + eu;
            float cn = sigmf(zf) * cS[ci] + sigmf(zi) * tanhf(zg);
            cS[ci] = cn;
            float hv = sigmf(zo) * tanhf(cn);
            g_hH[((size_t)t * BATCH + mb * 64 + r * 32 + prow) * HS + nb * 16 + eu] =
                __float2half(hv);
            __syncthreads();              // part consumed before next round's sts
        }

        // per-mb barrier (32 CTAs): release h(t) rows of this mb group
        if (tid == 0) {
            flag_arrive(ctr);
            flag_spin(ctr, (unsigned)(t + 1) * 32u);
        }
        __syncthreads();
    }
}

// ---------------- heads ----------------
__global__ void __launch_bounds__(256) heads_kernel(
    const float* __restrict__ Wmu, const float* __restrict__ bmu,
    const float* __restrict__ lstd, const float* __restrict__ Wv,
    const float* __restrict__ bv, float* __restrict__ out) {
    __shared__ float Wt[17 * HS];
    __shared__ float sig_s[16], bias_s[17];
    int tid = threadIdx.x;
    for (int i = tid; i < HS * ACTD; i += 256) {
        int k = i >> 4, a = i & 15;
        Wt[a * HS + k] = Wmu[(size_t)k * ACTD + a];
    }
    for (int i = tid; i < HS; i += 256) Wt[16 * HS + i] = Wv[i];
    if (tid < 16) { sig_s[tid] = expf(lstd[tid]); bias_s[tid] = bmu[tid]; }
    if (tid == 16) bias_s[16] = bv[0];
    __syncthreads();

    int warp = tid >> 5, lane = tid & 31;
    int step = gridDim.x * 8;
    for (int row = blockIdx.x * 8 + warp; row < TBROWS; row += step) {
        const HF* hh = g_hH + (size_t)row * HS;
        float acc[17];
#pragma unroll
        for (int a = 0; a < 17; a++) acc[a] = 0.f;
#pragma unroll 4
        for (int q = 0; q < 16; q++) {
            int idx = q * 32 + lane;
            float hv = __half2float(hh[idx]);
#pragma unroll
            for (int a = 0; a < 17; a++) acc[a] += hv * Wt[a * HS + idx];
        }
#pragma unroll
        for (int a = 0; a < 17; a++)
#pragma unroll
            for (int off = 16; off > 0; off >>= 1)
                acc[a] += __shfl_xor_sync(0xffffffffu, acc[a], off);
        if (lane < 16) {
            out[(size_t)row * ACTD + lane] = acc[lane] + bias_s[lane];
            out[(size_t)TBROWS * ACTD + (size_t)row * ACTD + lane] = sig_s[lane];
        }
        if (lane == 0)
            out[(size_t)TBROWS * ACTD * 2 + row] = acc[16] + bias_s[16];
    }
}

// ---------------- launch ----------------
extern "C" void kernel_launch(void* const* d_in, const int* in_sizes, int n_in,
                              void* d_out, int out_size) {
    const float* x     = (const float*)d_in[0];
    const float* W_enc = (const float*)d_in[1];
    const float* b_enc = (const float*)d_in[2];
    const float* Wi    = (const float*)d_in[3];
    const float* Wh    = (const float*)d_in[4];
    const float* b_l   = (const float*)d_in[5];
    const float* W_mu  = (const float*)d_in[6];
    const float* b_mu  = (const float*)d_in[7];
    const float* lstd  = (const float*)d_in[8];
    const float* W_v   = (const float*)d_in[9];
    const float* b_v   = (const float*)d_in[10];
    float* out = (float*)d_out;

    cudaFuncSetAttribute(xg_mma_kernel,   cudaFuncAttributeMaxDynamicSharedMemorySize, X_DYN);
    cudaFuncSetAttribute(scan_mma_kernel, cudaFuncAttributeMaxDynamicSharedMemorySize, S_DYN);

    prep_kernel<<<1024, 256>>>(Wi, Wh, b_l);
    enc_kernel<<<dim3(HIDD / 64, TBROWS / 64), 256>>>(x, W_enc, b_enc);
    xg_mma_kernel<<<dim3(32, TBROWS / 64), 512, X_DYN>>>();
    scan_mma_kernel<<<NCTA, 512, S_DYN>>>();
    heads_kernel<<<1024, 256>>>(W_mu, b_mu, lstd, W_v, b_v, out);
}

// round 13
// speedup vs baseline: 2.1673x; 1.4177x over previous
#include <cuda_runtime.h>
#include <cuda_fp16.h>
#include <math.h>
#include <stdint.h>

#define T_STEPS 256
#define BATCH   256
#define OBSD    128
#define HIDD    256
#define HS      512
#define G4      2048
#define ACTD    16
#define TBROWS  (T_STEPS * BATCH)
#define NCTA    128
typedef __half HF;

// ---------------- scratch (static device arrays; no cudaMalloc) ----------------
__device__ __align__(16) HF    g_fH[(size_t)TBROWS * HIDD];   // feats fp16
__device__ __align__(16) HF    g_hH[(size_t)TBROWS * HS];     // h fp16
__device__ __align__(16) HF    g_Wh[(size_t)G4 * HS];         // [n][k] permuted+transposed fp16
__device__ __align__(16) HF    g_Wi[(size_t)G4 * HIDD];
__device__ __align__(16) float g_bP[G4];
__device__ __align__(128) unsigned g_cntA[128];               // per-mb barrier counters (mb*32)

__device__ __forceinline__ float sigmf(float x) { return 1.0f / (1.0f + expf(-x)); }
__device__ __forceinline__ float geluf(float v) {
    float u = 0.7978845608028654f * (v + 0.044715f * v * v * v);
    return 0.5f * v * (1.0f + tanhf(u));
}
__device__ __forceinline__ uint32_t smem_u32(const void* p) {
    uint32_t a;
    asm("{ .reg .u64 t; cvta.to.shared.u64 t, %1; cvt.u32.u64 %0, t; }" : "=r"(a) : "l"(p));
    return a;
}
__device__ __forceinline__ void ldmx4(uint32_t addr, uint32_t* r) {
    asm volatile("ldmatrix.sync.aligned.m8n8.x4.shared.b16 {%0,%1,%2,%3}, [%4];"
        : "=r"(r[0]), "=r"(r[1]), "=r"(r[2]), "=r"(r[3]) : "r"(addr));
}
__device__ __forceinline__ void mma16816(float* d, const uint32_t* a, const uint32_t* b) {
    asm volatile("mma.sync.aligned.m16n8k16.row.col.f32.f16.f16.f32 "
        "{%0,%1,%2,%3}, {%4,%5,%6,%7}, {%8,%9}, {%0,%1,%2,%3};"
        : "+f"(d[0]), "+f"(d[1]), "+f"(d[2]), "+f"(d[3])
        : "r"(a[0]), "r"(a[1]), "r"(a[2]), "r"(a[3]), "r"(b[0]), "r"(b[1]));
}
#define CP_COMMIT() asm volatile("cp.async.commit_group;" ::: "memory")
#define CP_WAIT0()  asm volatile("cp.async.wait_group 0;" ::: "memory")
#define CP_WAIT1()  asm volatile("cp.async.wait_group 1;" ::: "memory")
__device__ __forceinline__ void flag_arrive(unsigned* f) {
    asm volatile("red.release.gpu.global.add.u32 [%0], %1;" :: "l"(f), "r"(1u) : "memory");
}
__device__ __forceinline__ void flag_spin(const unsigned* f, unsigned target) {
    unsigned v;
    do {
        asm volatile("ld.acquire.gpu.global.u32 %0, [%1];" : "=r"(v) : "l"(f) : "memory");
    } while (v < target);
}

// A stage stride: 136 halves (272B, ≡16 mod 128 -> conflict-free ldmatrix)
#define AST 136
#define CHUNK_BYTES 17408          // 64 x 136 halves
// ---- scan SMEM map (bytes) ----
#define S_WH   0                   // Wh slice 64x520 halves = 66560
#define S_WI   66560               // Wi slice 64x264 halves = 33792
#define S_HB0  100352              // h stage buffers, 17408 each
#define S_HB1  117760
#define S_PART 100352              // part[4][32][68] f32 = 34816 -> aliases both h bufs
#define S_FB   135168              // feats stage: 2 sub-chunks of 17408 = 34816
#define S_CS   169984              // cell state 64x16 fp32 = 4096
#define S_BS   174080              // bias slice 64 f32 = 256
#define S_DYN  174336
#define WST_H  520
#define WST_I  264

// cp.async one K=128 chunk (64 rows) of fp16 A into stage buffer (512 thr)
__device__ __forceinline__ void stage_cp(uint32_t dst, const HF* src, int ld, int tid) {
#pragma unroll
    for (int p = 0; p < 2; p++) {
        int j = tid + p * 512;
        int r = j >> 4, cb = j & 15;
        const HF* s = src + (size_t)r * ld + cb * 8;
        uint32_t d = dst + r * 272 + cb * 16;
        asm volatile("cp.async.cg.shared.global [%0], [%1], 16;" :: "r"(d), "l"(s));
    }
}

// Warp (ng in [0,4), kg in [0,4)): m64 x n16 tile, single fp16 pass,
// 2 ksteps (kg*2, kg*2+1) of a 128-col A chunk against W ksteps wkbase+...
__device__ __forceinline__ void mma_1p(uint32_t aBuf, uint32_t wBuf, int wst,
                                       int kg, int wkbase, int ng, int lane,
                                       float acc[4][2][4]) {
#pragma unroll
    for (int s = 0; s < 2; s++) {
        int lks = kg * 2 + s;
        int wks = wkbase + lks;
        uint32_t bh[4];
        int nrow = ng * 16 + (lane & 7) + ((lane >> 4) << 3);
        int kcol = wks * 16 + ((lane >> 3) & 1) * 8;
        ldmx4(wBuf + (nrow * wst + kcol) * 2, bh);
#pragma unroll
        for (int mt = 0; mt < 4; mt++) {
            uint32_t ah[4];
            int row = mt * 16 + (lane & 15);
            int col = lks * 16 + ((lane >> 4) << 3);
            ldmx4(aBuf + (row * AST + col) * 2, ah);
#pragma unroll
            for (int q = 0; q < 2; q++)
                mma16816(acc[mt][q], ah, &bh[q * 2]);
        }
    }
}

// STS k-split partials for round r (rows [32r,32r+32)): part[kg][32][68]
__device__ __forceinline__ void sts_part(float* part, float acc[4][2][4],
                                         int r, int kg, int ng, int lane) {
#pragma unroll
    for (int mt2 = 0; mt2 < 2; mt2++) {
        int mt = r * 2 + mt2;
#pragma unroll
        for (int nt = 0; nt < 2; nt++) {
            int row0 = mt2 * 16 + (lane >> 2);
            int col = ng * 16 + nt * 8 + (lane & 3) * 2;
            *(float2*)&part[(kg * 32 + row0) * 68 + col] = *(float2*)&acc[mt][nt][0];
            *(float2*)&part[(kg * 32 + row0 + 8) * 68 + col] = *(float2*)&acc[mt][nt][2];
        }
    }
}

// ---------------- prep: permuted+transposed fp16 weights (single precision pass) ----------------
__global__ void prep_kernel(const float* __restrict__ Wi, const float* __restrict__ Wh,
                            const float* __restrict__ bl) {
    int stride = gridDim.x * blockDim.x;
    int idx = blockIdx.x * blockDim.x + threadIdx.x;
    for (int i = idx; i < G4 * HS; i += stride) {
        int n = i >> 9, k = i & (HS - 1);
        g_Wh[i] = __float2half(Wh[(size_t)k * G4 + (n & 3) * HS + (n >> 2)]);
    }
    for (int i = idx; i < G4 * HIDD; i += stride) {
        int n = i >> 8, k = i & (HIDD - 1);
        g_Wi[i] = __float2half(Wi[(size_t)k * G4 + (n & 3) * HS + (n >> 2)]);
    }
    for (int i = idx; i < G4; i += stride)
        g_bP[i] = bl[(i & 3) * HS + (i >> 2)];
    if (idx < 128) g_cntA[idx] = 0;
}

// ---------------- encoder: feats = gelu(x@W_enc + b) -> fp16 ----------------
__global__ void __launch_bounds__(256) enc_kernel(const float* __restrict__ A,
                                                  const float* __restrict__ B,
                                                  const float* __restrict__ bias) {
    __shared__ float As[64 * 68];
    __shared__ float Bs[64 * 64];
    int nb = blockIdx.x, mb = blockIdx.y, tid = threadIdx.x;
    int tn = tid & 15, tm = tid >> 4;
    float acc[4][4];
#pragma unroll
    for (int i = 0; i < 4; i++)
#pragma unroll
        for (int j = 0; j < 4; j++) acc[i][j] = 0.f;
    for (int kc = 0; kc < 2; kc++) {
        __syncthreads();
#pragma unroll
        for (int p = 0; p < 4; p++) {
            int idx = p * 256 + tid, r = idx >> 4, c4 = (idx & 15) << 2;
            *(float4*)&As[r * 68 + c4] = *(const float4*)&A[(size_t)(mb * 64 + r) * OBSD + kc * 64 + c4];
            *(float4*)&Bs[r * 64 + c4] = *(const float4*)&B[(size_t)(kc * 64 + r) * HIDD + nb * 64 + c4];
        }
        __syncthreads();
#pragma unroll 8
        for (int kk = 0; kk < 64; kk++) {
            float4 w = *(const float4*)&Bs[kk * 64 + tn * 4];
#pragma unroll
            for (int i = 0; i < 4; i++) {
                float a = As[(tm * 4 + i) * 68 + kk];
                acc[i][0] += a * w.x; acc[i][1] += a * w.y;
                acc[i][2] += a * w.z; acc[i][3] += a * w.w;
            }
        }
    }
    int n0 = nb * 64 + tn * 4;
    float4 bb = *(const float4*)&bias[n0];
#pragma unroll
    for (int i = 0; i < 4; i++) {
        int row = mb * 64 + tm * 4 + i;
        __align__(8) HF hb[4];
        hb[0] = __float2half(geluf(acc[i][0] + bb.x));
        hb[1] = __float2half(geluf(acc[i][1] + bb.y));
        hb[2] = __float2half(geluf(acc[i][2] + bb.z));
        hb[3] = __float2half(geluf(acc[i][3] + bb.w));
        *(int2*)(g_fH + (size_t)row * HIDD + n0) = *(int2*)hb;
    }
}

// ---------------- fused persistent LSTM scan (x_gates computed inline) ----------------
// 128 CTAs = 4 mb(64 batch) x 32 nb(64 gate cols). 16 warps = 4 ng x 4 kg.
// z = h(t-1)@Wh + feats(t)@Wi + b, all via single-pass fp16 HMMA.
// feats tile for step t+1 is staged during the inter-CTA barrier spin.
__global__ void __launch_bounds__(512) scan_mma_kernel() {
    extern __shared__ char sm[];
    uint32_t sb = smem_u32(sm);
    float* cS = (float*)(sm + S_CS);
    float* part = (float*)(sm + S_PART);
    float* bS = (float*)(sm + S_BS);
    int tid = threadIdx.x, lane = tid & 31, wid = tid >> 5;
    int mb = blockIdx.x >> 5, nb = blockIdx.x & 31;
    int ng = wid & 3, kg = wid >> 2;
    unsigned* ctr = &g_cntA[mb * 32];

    {   // resident Wh slice [64][512] + Wi slice [64][256] + bias
        HF* Wh = (HF*)(sm + S_WH);
        HF* Wi = (HF*)(sm + S_WI);
        const HF* sh = g_Wh + (size_t)(nb * 64) * HS;
        const HF* si = g_Wi + (size_t)(nb * 64) * HIDD;
        for (int i = tid; i < 4096; i += 512) {
            int r = i >> 6, c8 = (i & 63) * 8;
            *(int4*)&Wh[r * WST_H + c8] = *(const int4*)&sh[(size_t)r * HS + c8];
        }
        for (int i = tid; i < 2048; i += 512) {
            int r = i >> 5, c8 = (i & 31) * 8;
            *(int4*)&Wi[r * WST_I + c8] = *(const int4*)&si[(size_t)r * HIDD + c8];
        }
        if (tid < 64) bS[tid] = g_bP[nb * 64 + tid];
    }
    for (int i = tid; i < 64 * 16; i += 512) cS[i] = 0.f;
    __syncthreads();

    int prow = tid >> 4, eu = tid & 15;    // epilogue: 1 unit / thread / round
    const uint32_t bufs[2] = { sb + S_HB0, sb + S_HB1 };
    const uint32_t fb = sb + S_FB;

    // prologue: stage feats tile for t=0
    {
        const HF* F = g_fH + (size_t)(mb * 64) * HIDD;
        stage_cp(fb, F, HIDD, tid);
        stage_cp(fb + CHUNK_BYTES, F + 128, HIDD, tid);
        CP_COMMIT();
    }

#pragma unroll 1
    for (int t = 0; t < T_STEPS; t++) {
        float acc[4][2][4];
#pragma unroll
        for (int a = 0; a < 4; a++)
#pragma unroll
            for (int b = 0; b < 2; b++)
#pragma unroll
                for (int e = 0; e < 4; e++) acc[a][b][e] = 0.f;

        const HF* Ah = g_hH + ((size_t)(t - 1) * BATCH + mb * 64) * HS;
        if (t > 0) {
            stage_cp(bufs[0], Ah, HS, tid);         // h chunk0 in flight
            CP_COMMIT();
            CP_WAIT1();                              // feats ready (h0 may pend)
        } else {
            CP_WAIT0();
        }
        __syncthreads();

        // feats @ Wi (16 ksteps as two 128-col sub-chunks)
        mma_1p(fb, sb + S_WI, WST_I, kg, 0, ng, lane, acc);
        mma_1p(fb + CHUNK_BYTES, sb + S_WI, WST_I, kg, 8, ng, lane, acc);

        if (t > 0) {
#pragma unroll 1
            for (int ch = 0; ch < 4; ch++) {
                CP_WAIT0();
                __syncthreads();
                if (ch < 3) {
                    stage_cp(bufs[(ch + 1) & 1], Ah + (ch + 1) * 128, HS, tid);
                    CP_COMMIT();
                }
                mma_1p(bufs[ch & 1], sb + S_WH, WST_H, kg, ch * 8, ng, lane, acc);
            }
        }
        __syncthreads();              // all MMAs done; h bufs dead -> part alias safe

        // two epilogue rounds of 32 rows each
#pragma unroll
        for (int r = 0; r < 2; r++) {
            sts_part(part, acc, r, kg, ng, lane);
            __syncthreads();
            float g0 = 0.f, g1 = 0.f, g2 = 0.f, g3 = 0.f;
#pragma unroll
            for (int k = 0; k < 4; k++) {
                float4 p = *(const float4*)&part[(k * 32 + prow) * 68 + eu * 4];
                g0 += p.x; g1 += p.y; g2 += p.z; g3 += p.w;
            }
            float zi = g0 + bS[eu * 4 + 0];
            float zf = g1 + bS[eu * 4 + 1];
            float zg = g2 + bS[eu * 4 + 2];
            float zo = g3 + bS[eu * 4 + 3];
            int ci = (r * 32 + prow) * 16 + eu;
            float cn = sigmf(zf) * cS[ci] + sigmf(zi) * tanhf(zg);
            cS[ci] = cn;
            float hv = sigmf(zo) * tanhf(cn);
            g_hH[((size_t)t * BATCH + mb * 64 + r * 32 + prow) * HS + nb * 16 + eu] =
                __float2half(hv);
            __syncthreads();          // part consumed before next round's sts
        }

        // release h(t); stage feats(t+1) during the spin
        if (tid == 0) flag_arrive(ctr);
        if (t + 1 < T_STEPS) {
            const HF* F = g_fH + ((size_t)(t + 1) * BATCH + mb * 64) * HIDD;
            stage_cp(fb, F, HIDD, tid);
            stage_cp(fb + CHUNK_BYTES, F + 128, HIDD, tid);
            CP_COMMIT();
        }
        if (tid == 0) flag_spin(ctr, (unsigned)(t + 1) * 32u);
        __syncthreads();
    }
}

// ---------------- heads ----------------
__global__ void __launch_bounds__(256) heads_kernel(
    const float* __restrict__ Wmu, const float* __restrict__ bmu,
    const float* __restrict__ lstd, const float* __restrict__ Wv,
    const float* __restrict__ bv, float* __restrict__ out) {
    __shared__ float Wt[17 * HS];
    __shared__ float sig_s[16], bias_s[17];
    int tid = threadIdx.x;
    for (int i = tid; i < HS * ACTD; i += 256) {
        int k = i >> 4, a = i & 15;
        Wt[a * HS + k] = Wmu[(size_t)k * ACTD + a];
    }
    for (int i = tid; i < HS; i += 256) Wt[16 * HS + i] = Wv[i];
    if (tid < 16) { sig_s[tid] = expf(lstd[tid]); bias_s[tid] = bmu[tid]; }
    if (tid == 16) bias_s[16] = bv[0];
    __syncthreads();

    int warp = tid >> 5, lane = tid & 31;
    int step = gridDim.x * 8;
    for (int row = blockIdx.x * 8 + warp; row < TBROWS; row += step) {
        const HF* hh = g_hH + (size_t)row * HS;
        float acc[17];
#pragma unroll
        for (int a = 0; a < 17; a++) acc[a] = 0.f;
#pragma unroll 4
        for (int q = 0; q < 16; q++) {
            int idx = q * 32 + lane;
            float hv = __half2float(hh[idx]);
#pragma unroll
            for (int a = 0; a < 17; a++) acc[a] += hv * Wt[a * HS + idx];
        }
#pragma unroll
        for (int a = 0; a < 17; a++)
#pragma unroll
            for (int off = 16; off > 0; off >>= 1)
                acc[a] += __shfl_xor_sync(0xffffffffu, acc[a], off);
        if (lane < 16) {
            out[(size_t)row * ACTD + lane] = acc[lane] + bias_s[lane];
            out[(size_t)TBROWS * ACTD + (size_t)row * ACTD + lane] = sig_s[lane];
        }
        if (lane == 0)
            out[(size_t)TBROWS * ACTD * 2 + row] = acc[16] + bias_s[16];
    }
}

// ---------------- launch ----------------
extern "C" void kernel_launch(void* const* d_in, const int* in_sizes, int n_in,
                              void* d_out, int out_size) {
    const float* x     = (const float*)d_in[0];
    const float* W_enc = (const float*)d_in[1];
    const float* b_enc = (const float*)d_in[2];
    const float* Wi    = (const float*)d_in[3];
    const float* Wh    = (const float*)d_in[4];
    const float* b_l   = (const float*)d_in[5];
    const float* W_mu  = (const float*)d_in[6];
    const float* b_mu  = (const float*)d_in[7];
    const float* lstd  = (const float*)d_in[8];
    const float* W_v   = (const float*)d_in[9];
    const float* b_v   = (const float*)d_in[10];
    float* out = (float*)d_out;

    cudaFuncSetAttribute(scan_mma_kernel, cudaFuncAttributeMaxDynamicSharedMemorySize, S_DYN);

    prep_kernel<<<1024, 256>>>(Wi, Wh, b_l);
    enc_kernel<<<dim3(HIDD / 64, TBROWS / 64), 256>>>(x, W_enc, b_enc);
    scan_mma_kernel<<<NCTA, 512, S_DYN>>>();
    heads_kernel<<<1024, 256>>>(W_mu, b_mu, lstd, W_v, b_v, out);
}

// round 14
// speedup vs baseline: 2.3512x; 1.0849x over previous
#include <cuda_runtime.h>
#include <cuda_fp16.h>
#include <math.h>
#include <stdint.h>

#define T_STEPS 256
#define BATCH   256
#define OBSD    128
#define HIDD    256
#define HS      512
#define G4      2048
#define ACTD    16
#define TBROWS  (T_STEPS * BATCH)
#define NCTA    128
typedef __half HF;

// ---------------- scratch (static device arrays; no cudaMalloc) ----------------
__device__ __align__(16) HF    g_fH[(size_t)TBROWS * HIDD];   // feats fp16
__device__ __align__(16) HF    g_hH[(size_t)TBROWS * HS];     // h fp16
__device__ __align__(16) HF    g_Wh[(size_t)G4 * HS];         // [n][k] permuted+transposed fp16
__device__ __align__(16) HF    g_Wi[(size_t)G4 * HIDD];
__device__ __align__(16) float g_bP[G4];
__device__ __align__(128) unsigned g_cntA[128];               // per-mb barrier counters (mb*32)

__device__ __forceinline__ float sigmf(float x) { return 1.0f / (1.0f + expf(-x)); }
__device__ __forceinline__ float geluf(float v) {
    float u = 0.7978845608028654f * (v + 0.044715f * v * v * v);
    return 0.5f * v * (1.0f + tanhf(u));
}
__device__ __forceinline__ uint32_t smem_u32(const void* p) {
    uint32_t a;
    asm("{ .reg .u64 t; cvta.to.shared.u64 t, %1; cvt.u32.u64 %0, t; }" : "=r"(a) : "l"(p));
    return a;
}
__device__ __forceinline__ void ldmx4(uint32_t addr, uint32_t* r) {
    asm volatile("ldmatrix.sync.aligned.m8n8.x4.shared.b16 {%0,%1,%2,%3}, [%4];"
        : "=r"(r[0]), "=r"(r[1]), "=r"(r[2]), "=r"(r[3]) : "r"(addr));
}
__device__ __forceinline__ void mma16816(float* d, const uint32_t* a, const uint32_t* b) {
    asm volatile("mma.sync.aligned.m16n8k16.row.col.f32.f16.f16.f32 "
        "{%0,%1,%2,%3}, {%4,%5,%6,%7}, {%8,%9}, {%0,%1,%2,%3};"
        : "+f"(d[0]), "+f"(d[1]), "+f"(d[2]), "+f"(d[3])
        : "r"(a[0]), "r"(a[1]), "r"(a[2]), "r"(a[3]), "r"(b[0]), "r"(b[1]));
}
#define CP_COMMIT() asm volatile("cp.async.commit_group;" ::: "memory")
#define CP_WAIT0()  asm volatile("cp.async.wait_group 0;" ::: "memory")
#define CP_WAIT1()  asm volatile("cp.async.wait_group 1;" ::: "memory")
__device__ __forceinline__ void flag_arrive(unsigned* f) {
    asm volatile("red.release.gpu.global.add.u32 [%0], %1;" :: "l"(f), "r"(1u) : "memory");
}
__device__ __forceinline__ void flag_spin(const unsigned* f, unsigned target) {
    unsigned v;
    do {
        asm volatile("ld.acquire.gpu.global.u32 %0, [%1];" : "=r"(v) : "l"(f) : "memory");
    } while (v < target);
}

// A stage stride: 136 halves (272B, ≡16 mod 128 -> conflict-free ldmatrix)
#define AST 136
#define CHUNK_BYTES 17408          // 64 x 136 halves
// ---- scan SMEM map (bytes) ----
#define S_WH   0                   // Wh slice 64x520 halves = 66560
#define S_WI   66560               // Wi slice 64x264 halves = 33792
#define S_HB   100352              // h stage: 4 chunks x 17408 = 69632
#define S_PART 100352              // part[4][64][68] f32 = 69632 -> aliases all h bufs
#define S_FB   169984              // feats stage: 2 sub-chunks of 17408 = 34816
#define S_CS   204800              // cell state 64x16 fp32 = 4096
#define S_BS   208896              // bias slice 64 f32 = 256
#define S_DYN  209152
#define WST_H  520
#define WST_I  264

// cp.async one K=128 chunk (64 rows) of fp16 A into stage buffer (512 thr)
__device__ __forceinline__ void stage_cp(uint32_t dst, const HF* src, int ld, int tid) {
#pragma unroll
    for (int p = 0; p < 2; p++) {
        int j = tid + p * 512;
        int r = j >> 4, cb = j & 15;
        const HF* s = src + (size_t)r * ld + cb * 8;
        uint32_t d = dst + r * 272 + cb * 16;
        asm volatile("cp.async.cg.shared.global [%0], [%1], 16;" :: "r"(d), "l"(s));
    }
}
// stage all 4 h chunks (K=512) in one burst
__device__ __forceinline__ void stage_h_all(uint32_t dst, const HF* src, int tid) {
#pragma unroll
    for (int ch = 0; ch < 4; ch++)
        stage_cp(dst + ch * CHUNK_BYTES, src + ch * 128, HS, tid);
}

// Warp (ng in [0,4), kg in [0,4)): m64 x n16 tile, single fp16 pass,
// 2 ksteps (kg*2, kg*2+1) of a 128-col A chunk against W ksteps wkbase+...
__device__ __forceinline__ void mma_1p(uint32_t aBuf, uint32_t wBuf, int wst,
                                       int kg, int wkbase, int ng, int lane,
                                       float acc[4][2][4]) {
#pragma unroll
    for (int s = 0; s < 2; s++) {
        int lks = kg * 2 + s;
        int wks = wkbase + lks;
        uint32_t bh[4];
        int nrow = ng * 16 + (lane & 7) + ((lane >> 4) << 3);
        int kcol = wks * 16 + ((lane >> 3) & 1) * 8;
        ldmx4(wBuf + (nrow * wst + kcol) * 2, bh);
#pragma unroll
        for (int mt = 0; mt < 4; mt++) {
            uint32_t ah[4];
            int row = mt * 16 + (lane & 15);
            int col = lks * 16 + ((lane >> 4) << 3);
            ldmx4(aBuf + (row * AST + col) * 2, ah);
#pragma unroll
            for (int q = 0; q < 2; q++)
                mma16816(acc[mt][q], ah, &bh[q * 2]);
        }
    }
}

// STS all k-split partials: part[kg][64][68]
__device__ __forceinline__ void sts_part_all(float* part, float acc[4][2][4],
                                             int kg, int ng, int lane) {
#pragma unroll
    for (int mt = 0; mt < 4; mt++)
#pragma unroll
        for (int nt = 0; nt < 2; nt++) {
            int row0 = mt * 16 + (lane >> 2);
            int col = ng * 16 + nt * 8 + (lane & 3) * 2;
            *(float2*)&part[(kg * 64 + row0) * 68 + col] = *(float2*)&acc[mt][nt][0];
            *(float2*)&part[(kg * 64 + row0 + 8) * 68 + col] = *(float2*)&acc[mt][nt][2];
        }
}

// ---------------- prep: permuted+transposed fp16 weights ----------------
__global__ void prep_kernel(const float* __restrict__ Wi, const float* __restrict__ Wh,
                            const float* __restrict__ bl) {
    int stride = gridDim.x * blockDim.x;
    int idx = blockIdx.x * blockDim.x + threadIdx.x;
    for (int i = idx; i < G4 * HS; i += stride) {
        int n = i >> 9, k = i & (HS - 1);
        g_Wh[i] = __float2half(Wh[(size_t)k * G4 + (n & 3) * HS + (n >> 2)]);
    }
    for (int i = idx; i < G4 * HIDD; i += stride) {
        int n = i >> 8, k = i & (HIDD - 1);
        g_Wi[i] = __float2half(Wi[(size_t)k * G4 + (n & 3) * HS + (n >> 2)]);
    }
    for (int i = idx; i < G4; i += stride)
        g_bP[i] = bl[(i & 3) * HS + (i >> 2)];
    if (idx < 128) g_cntA[idx] = 0;
}

// ---------------- encoder: feats = gelu(x@W_enc + b) -> fp16 ----------------
__global__ void __launch_bounds__(256) enc_kernel(const float* __restrict__ A,
                                                  const float* __restrict__ B,
                                                  const float* __restrict__ bias) {
    __shared__ float As[64 * 68];
    __shared__ float Bs[64 * 64];
    int nb = blockIdx.x, mb = blockIdx.y, tid = threadIdx.x;
    int tn = tid & 15, tm = tid >> 4;
    float acc[4][4];
#pragma unroll
    for (int i = 0; i < 4; i++)
#pragma unroll
        for (int j = 0; j < 4; j++) acc[i][j] = 0.f;
    for (int kc = 0; kc < 2; kc++) {
        __syncthreads();
#pragma unroll
        for (int p = 0; p < 4; p++) {
            int idx = p * 256 + tid, r = idx >> 4, c4 = (idx & 15) << 2;
            *(float4*)&As[r * 68 + c4] = *(const float4*)&A[(size_t)(mb * 64 + r) * OBSD + kc * 64 + c4];
            *(float4*)&Bs[r * 64 + c4] = *(const float4*)&B[(size_t)(kc * 64 + r) * HIDD + nb * 64 + c4];
        }
        __syncthreads();
#pragma unroll 8
        for (int kk = 0; kk < 64; kk++) {
            float4 w = *(const float4*)&Bs[kk * 64 + tn * 4];
#pragma unroll
            for (int i = 0; i < 4; i++) {
                float a = As[(tm * 4 + i) * 68 + kk];
                acc[i][0] += a * w.x; acc[i][1] += a * w.y;
                acc[i][2] += a * w.z; acc[i][3] += a * w.w;
            }
        }
    }
    int n0 = nb * 64 + tn * 4;
    float4 bb = *(const float4*)&bias[n0];
#pragma unroll
    for (int i = 0; i < 4; i++) {
        int row = mb * 64 + tm * 4 + i;
        __align__(8) HF hb[4];
        hb[0] = __float2half(geluf(acc[i][0] + bb.x));
        hb[1] = __float2half(geluf(acc[i][1] + bb.y));
        hb[2] = __float2half(geluf(acc[i][2] + bb.z));
        hb[3] = __float2half(geluf(acc[i][3] + bb.w));
        *(int2*)(g_fH + (size_t)row * HIDD + n0) = *(int2*)hb;
    }
}

// ---------------- fused persistent LSTM scan ----------------
// 128 CTAs = 4 mb(64 batch) x 32 nb(64 gate cols). 16 warps = 4 ng x 4 kg.
// z = h(t-1)@Wh + feats(t)@Wi + b. All 4 h chunks staged in ONE cp.async burst;
// feats(t+1) staged during the inter-CTA barrier spin; single-round epilogue.
__global__ void __launch_bounds__(512) scan_mma_kernel() {
    extern __shared__ char sm[];
    uint32_t sb = smem_u32(sm);
    float* cS = (float*)(sm + S_CS);
    float* part = (float*)(sm + S_PART);
    float* bS = (float*)(sm + S_BS);
    int tid = threadIdx.x, lane = tid & 31, wid = tid >> 5;
    int mb = blockIdx.x >> 5, nb = blockIdx.x & 31;
    int ng = wid & 3, kg = wid >> 2;
    unsigned* ctr = &g_cntA[mb * 32];

    {   // resident Wh slice [64][512] + Wi slice [64][256] + bias
        HF* Wh = (HF*)(sm + S_WH);
        HF* Wi = (HF*)(sm + S_WI);
        const HF* sh = g_Wh + (size_t)(nb * 64) * HS;
        const HF* si = g_Wi + (size_t)(nb * 64) * HIDD;
        for (int i = tid; i < 4096; i += 512) {
            int r = i >> 6, c8 = (i & 63) * 8;
            *(int4*)&Wh[r * WST_H + c8] = *(const int4*)&sh[(size_t)r * HS + c8];
        }
        for (int i = tid; i < 2048; i += 512) {
            int r = i >> 5, c8 = (i & 31) * 8;
            *(int4*)&Wi[r * WST_I + c8] = *(const int4*)&si[(size_t)r * HIDD + c8];
        }
        if (tid < 64) bS[tid] = g_bP[nb * 64 + tid];
    }
    for (int i = tid; i < 64 * 16; i += 512) cS[i] = 0.f;
    __syncthreads();

    int prow = tid >> 4, eu = tid & 15;    // epilogue rows prow, prow+32; unit eu
    const uint32_t hb = sb + S_HB;
    const uint32_t fb = sb + S_FB;

    // prologue: stage feats tile for t=0
    {
        const HF* F = g_fH + (size_t)(mb * 64) * HIDD;
        stage_cp(fb, F, HIDD, tid);
        stage_cp(fb + CHUNK_BYTES, F + 128, HIDD, tid);
        CP_COMMIT();
    }

#pragma unroll 1
    for (int t = 0; t < T_STEPS; t++) {
        float acc[4][2][4];
#pragma unroll
        for (int a = 0; a < 4; a++)
#pragma unroll
            for (int b = 0; b < 2; b++)
#pragma unroll
                for (int e = 0; e < 4; e++) acc[a][b][e] = 0.f;

        if (t > 0) {
            // burst-stage ALL 4 h chunks (one commit, one wait)
            const HF* Ah = g_hH + ((size_t)(t - 1) * BATCH + mb * 64) * HS;
            stage_h_all(hb, Ah, tid);
            CP_COMMIT();
            CP_WAIT1();                     // feats(t) done; h may pend
        } else {
            CP_WAIT0();
        }
        __syncthreads();

        // feats @ Wi (16 ksteps as two 128-col sub-chunks) — overlaps h staging
        mma_1p(fb, sb + S_WI, WST_I, kg, 0, ng, lane, acc);
        mma_1p(fb + CHUNK_BYTES, sb + S_WI, WST_I, kg, 8, ng, lane, acc);

        if (t > 0) {
            CP_WAIT0();                     // all h chunks resident
            __syncthreads();
#pragma unroll
            for (int ch = 0; ch < 4; ch++)
                mma_1p(hb + ch * CHUNK_BYTES, sb + S_WH, WST_H, kg, ch * 8, ng, lane, acc);
        }
        __syncthreads();                    // all MMAs done; h bufs dead -> part alias safe

        // single-round epilogue
        sts_part_all(part, acc, kg, ng, lane);
        __syncthreads();
#pragma unroll
        for (int r = 0; r < 2; r++) {
            int row = r * 32 + prow;
            float g0 = 0.f, g1 = 0.f, g2 = 0.f, g3 = 0.f;
#pragma unroll
            for (int k = 0; k < 4; k++) {
                float4 p = *(const float4*)&part[(k * 64 + row) * 68 + eu * 4];
                g0 += p.x; g1 += p.y; g2 += p.z; g3 += p.w;
            }
            float zi = g0 + bS[eu * 4 + 0];
            float zf = g1 + bS[eu * 4 + 1];
            float zg = g2 + bS[eu * 4 + 2];
            float zo = g3 + bS[eu * 4 + 3];
            int ci = row * 16 + eu;
            float cn = sigmf(zf) * cS[ci] + sigmf(zi) * tanhf(zg);
            cS[ci] = cn;
            float hv = sigmf(zo) * tanhf(cn);
            g_hH[((size_t)t * BATCH + mb * 64 + row) * HS + nb * 16 + eu] = __float2half(hv);
        }

        // release h(t); stage feats(t+1) during the spin
        __syncthreads();                    // h stores done CTA-wide before arrive
        if (tid == 0) flag_arrive(ctr);
        if (t + 1 < T_STEPS) {
            const HF* F = g_fH + ((size_t)(t + 1) * BATCH + mb * 64) * HIDD;
            stage_cp(fb, F, HIDD, tid);
            stage_cp(fb + CHUNK_BYTES, F + 128, HIDD, tid);
            CP_COMMIT();
        }
        if (tid == 0) flag_spin(ctr, (unsigned)(t + 1) * 32u);
        __syncthreads();                    // also fences part reads vs next h staging
    }
}

// ---------------- heads: 2 rows per warp share every Wt LDS ----------------
__global__ void __launch_bounds__(256) heads_kernel(
    const float* __restrict__ Wmu, const float* __restrict__ bmu,
    const float* __restrict__ lstd, const float* __restrict__ Wv,
    const float* __restrict__ bv, float* __restrict__ out) {
    __shared__ float Wt[17 * HS];
    __shared__ float sig_s[16], bias_s[17];
    int tid = threadIdx.x;
    for (int i = tid; i < HS * ACTD; i += 256) {
        int k = i >> 4, a = i & 15;
        Wt[a * HS + k] = Wmu[(size_t)k * ACTD + a];
    }
    for (int i = tid; i < HS; i += 256) Wt[16 * HS + i] = Wv[i];
    if (tid < 16) { sig_s[tid] = expf(lstd[tid]); bias_s[tid] = bmu[tid]; }
    if (tid == 16) bias_s[16] = bv[0];
    __syncthreads();

    int warp = tid >> 5, lane = tid & 31;
    int step = gridDim.x * 16;
    for (int row = blockIdx.x * 16 + warp * 2; row < TBROWS; row += step) {
        const HF* h0 = g_hH + (size_t)row * HS;
        const HF* h1 = h0 + HS;
        float a0[17], a1[17];
#pragma unroll
        for (int a = 0; a < 17; a++) { a0[a] = 0.f; a1[a] = 0.f; }
#pragma unroll 4
        for (int q = 0; q < 16; q++) {
            int idx = q * 32 + lane;
            float v0 = __half2float(h0[idx]);
            float v1 = __half2float(h1[idx]);
#pragma unroll
            for (int a = 0; a < 17; a++) {
                float w = Wt[a * HS + idx];
                a0[a] += v0 * w; a1[a] += v1 * w;
            }
        }
#pragma unroll
        for (int a = 0; a < 17; a++)
#pragma unroll
            for (int off = 16; off > 0; off >>= 1) {
                a0[a] += __shfl_xor_sync(0xffffffffu, a0[a], off);
                a1[a] += __shfl_xor_sync(0xffffffffu, a1[a], off);
            }
        if (lane < 16) {
            out[(size_t)row * ACTD + lane] = a0[lane] + bias_s[lane];
            out[(size_t)(row + 1) * ACTD + lane] = a1[lane] + bias_s[lane];
            out[(size_t)TBROWS * ACTD + (size_t)row * ACTD + lane] = sig_s[lane];
            out[(size_t)TBROWS * ACTD + (size_t)(row + 1) * ACTD + lane] = sig_s[lane];
        }
        if (lane == 0) {
            out[(size_t)TBROWS * ACTD * 2 + row] = a0[16] + bias_s[16];
            out[(size_t)TBROWS * ACTD * 2 + row + 1] = a1[16] + bias_s[16];
        }
    }
}

// ---------------- launch ----------------
extern "C" void kernel_launch(void* const* d_in, const int* in_sizes, int n_in,
                              void* d_out, int out_size) {
    const float* x     = (const float*)d_in[0];
    const float* W_enc = (const float*)d_in[1];
    const float* b_enc = (const float*)d_in[2];
    const float* Wi    = (const float*)d_in[3];
    const float* Wh    = (const float*)d_in[4];
    const float* b_l   = (const float*)d_in[5];
    const float* W_mu  = (const float*)d_in[6];
    const float* b_mu  = (const float*)d_in[7];
    const float* lstd  = (const float*)d_in[8];
    const float* W_v   = (const float*)d_in[9];
    const float* b_v   = (const float*)d_in[10];
    float* out = (float*)d_out;

    cudaFuncSetAttribute(scan_mma_kernel, cudaFuncAttributeMaxDynamicSharedMemorySize, S_DYN);

    prep_kernel<<<1024, 256>>>(Wi, Wh, b_l);
    enc_kernel<<<dim3(HIDD / 64, TBROWS / 64), 256>>>(x, W_enc, b_enc);
    scan_mma_kernel<<<NCTA, 512, S_DYN>>>();
    heads_kernel<<<1024, 256>>>(W_mu, b_mu, lstd, W_v, b_v, out);
}